// round 14
// baseline (speedup 1.0000x reference)
#include <cuda_runtime.h>
#include <cuda_bf16.h>
#include <cstdint>

#define B 256
#define E 512
#define H 1024
#define G 3072          // 3*H
#define V 128000
#define VT 127988       // V - 12
#define BV (B*V)
#define BH (B*H)
#define TNB 2000        // ceil(VT/64)
#define TSTRIDE 2048
#define LOG2E 1.4426950408889634f

// ---------------- scratch (device globals; no allocations allowed) ----------------
__device__ __align__(16) float g_x[B*E];        // gathered embedding (fp32)
__device__ __align__(16) float g_gi[B*G];       // gi0 accumulator
__device__ __align__(16) float g_gh[B*G];       // gh0 accumulator
__device__ __align__(16) float g_gh2[B*G];      // gh1 accumulator
__device__ __align__(16) float g_gi1[B*G];      // gi1 accumulator
__device__ __align__(16) float g_p0[B*256];
__device__ __align__(16) float g_p1f[B*64];
__device__ __align__(16) __nv_bfloat16 g_p1b[B*64];
__device__ float g_head[B*12];      // log-softmaxed head
__device__ float g_off[B];          // head_lp[:,11] - lse_tail
__device__ float g_psum[B*TSTRIDE];
__device__ float g_h0buf[BH], g_h1buf[BH];   // fallback if d_out lacks hidden region

// ---------------- helpers ----------------
__device__ __forceinline__ void mma16816(float* d, const uint32_t* a, const uint32_t* b) {
    asm volatile(
        "mma.sync.aligned.m16n8k16.row.col.f32.bf16.bf16.f32 "
        "{%0,%1,%2,%3}, {%4,%5,%6,%7}, {%8,%9}, {%0,%1,%2,%3};\n"
        : "+f"(d[0]), "+f"(d[1]), "+f"(d[2]), "+f"(d[3])
        : "r"(a[0]), "r"(a[1]), "r"(a[2]), "r"(a[3]), "r"(b[0]), "r"(b[1]));
}

// tf32 MMA: operands are fp32 bit patterns (HW uses top 19 bits)
__device__ __forceinline__ void mma_tf32(float* d, const uint32_t* a, const uint32_t* b) {
    asm volatile(
        "mma.sync.aligned.m16n8k8.row.col.f32.tf32.tf32.f32 "
        "{%0,%1,%2,%3}, {%4,%5,%6,%7}, {%8,%9}, {%0,%1,%2,%3};\n"
        : "+f"(d[0]), "+f"(d[1]), "+f"(d[2]), "+f"(d[3])
        : "r"(a[0]), "r"(a[1]), "r"(a[2]), "r"(a[3]), "r"(b[0]), "r"(b[1]));
}

__device__ __forceinline__ void red2(float* p, float a, float b) {
    asm volatile("red.global.add.v2.f32 [%0], {%1, %2};" :: "l"(p), "f"(a), "f"(b) : "memory");
}

__device__ __forceinline__ uint32_t pk2(__nv_bfloat16 a, __nv_bfloat16 b) {
    __nv_bfloat162 t; t.x = a; t.y = b;
    return *(uint32_t*)&t;
}

__device__ __forceinline__ float ex2f_(float x) {
    float y; asm("ex2.approx.ftz.f32 %0, %1;" : "=f"(y) : "f"(x)); return y;
}
__device__ __forceinline__ float rcpf_(float x) {
    float y; asm("rcp.approx.ftz.f32 %0, %1;" : "=f"(y) : "f"(x)); return y;
}
__device__ __forceinline__ float fsig(float x)  { return rcpf_(1.f + ex2f_(-LOG2E * x)); }
__device__ __forceinline__ float ftanh(float x) { return 2.f * rcpf_(1.f + ex2f_(-2.f * LOG2E * x)) - 1.f; }

__device__ __forceinline__ uint32_t smem_u32(const void* p) {
    uint32_t a;
    asm("{ .reg .u64 t; cvta.to.shared.u64 t, %1; cvt.u32.u64 %0, t; }" : "=r"(a) : "l"(p));
    return a;
}
__device__ __forceinline__ void cpa16(uint32_t s, const void* g) {
    asm volatile("cp.async.cg.shared.global [%0], [%1], 16;" :: "r"(s), "l"(g) : "memory");
}

// ---------------- prep: gather x (fp32) + zero all GEMM accumulators ----------------
#define NXF4    (B*E/4)                              // 32768
#define NGF4    (B*G/4)                              // 196608 per gate buffer
#define ZERO_F4 (4*NGF4 + B*256/4 + B*64/4)          // 806912
#define PREP_BLOCKS ((NXF4 + ZERO_F4) / 256)         // 3280 exactly

__global__ void prep_kernel(const int* __restrict__ idx, const float* __restrict__ emb) {
    int i = blockIdx.x * 256 + threadIdx.x;
    if (i < NXF4) {
        int row = i >> 7;                            // E/4 = 128
        int c4  = (i & 127) * 4;
        float4 v = *(const float4*)(emb + (size_t)idx[row] * E + c4);
        *(float4*)(g_x + (size_t)row * E + c4) = v;
        return;
    }
    int j = i - NXF4;
    float4 z = make_float4(0.f, 0.f, 0.f, 0.f);
    if      (j < 1*NGF4) ((float4*)g_gi )[j]          = z;
    else if (j < 2*NGF4) ((float4*)g_gh )[j - 1*NGF4] = z;
    else if (j < 3*NGF4) ((float4*)g_gh2)[j - 2*NGF4] = z;
    else if (j < 4*NGF4) ((float4*)g_gi1)[j - 3*NGF4] = z;
    else if (j < 4*NGF4 + B*256/4) ((float4*)g_p0)[j - 4*NGF4] = z;
    else                 ((float4*)g_p1f)[j - 4*NGF4 - B*256/4] = z;
}

// ---------------- TF32 tensor-core GEMM body (3-stage cp.async pipeline) ----------------
// BM=64, BN=64, BK=32, 128 threads (4 warps 2m x 2n, warp tile 32x32).
// A, W fp32 in global -> cp.async, 3 smem stages, no conversion anywhere.
// C[m0:m0+64, n0:n0+64] += A[., k0s : k0s+np*32] @ W[., same]^T   (red.global output)
#define TILE_F  (64 * 36)              // floats per tile
#define SMEM_GEMM (3 * 2 * TILE_F * 4) // 55296 bytes

__device__ __forceinline__ void gemm_body(
    const float* __restrict__ A,
    const float* __restrict__ W, int K, int k0s, int npanels,
    float* __restrict__ C, int ldC, int n0, int m0)
{
    extern __shared__ float dsm[];
    float* As = dsm;                   // [3][64][36]
    float* Ws = dsm + 3 * TILE_F;      // [3][64][36]

    const int tid = threadIdx.x, lane = tid & 31, warp = tid >> 5;
    const int row2 = tid >> 1;            // 0..63 (load row)
    const int cf   = (tid & 1) * 16;      // float offset of 16-float half-row
    const int mwB  = (warp & 1) * 32;
    const int nwB  = (warp >> 1) * 32;

    float acc[2][4][4];
#pragma unroll
    for (int a = 0; a < 2; a++)
#pragma unroll
        for (int b = 0; b < 4; b++)
#pragma unroll
            for (int c = 0; c < 4; c++) acc[a][b][c] = 0.f;

    const uint32_t sAbase = smem_u32(As);
    const uint32_t sWbase = smem_u32(Ws);
    const uint32_t loff = (uint32_t)(row2 * 36 + cf) * 4;

    // prologue: issue panels 0 and 1
#pragma unroll
    for (int pp = 0; pp < 2; pp++) {
        if (pp < npanels) {
            int k0 = k0s + pp * 32;
            const float* ga = A + (size_t)(m0 + row2) * K + k0 + cf;
            const float* gw = W + (size_t)(n0 + row2) * K + k0 + cf;
            uint32_t sa = sAbase + (uint32_t)pp * (TILE_F * 4) + loff;
            uint32_t sw = sWbase + (uint32_t)pp * (TILE_F * 4) + loff;
#pragma unroll
            for (int c = 0; c < 4; c++) {
                cpa16(sa + c * 16, ga + c * 4);
                cpa16(sw + c * 16, gw + c * 4);
            }
            asm volatile("cp.async.commit_group;" ::: "memory");
        }
    }

    for (int p = 0; p < npanels; p++) {
        // issue panel p+2 into buffer (p+2)%3
        if (p + 2 < npanels) {
            int k0 = k0s + (p + 2) * 32;
            int buf = (p + 2) % 3;
            const float* ga = A + (size_t)(m0 + row2) * K + k0 + cf;
            const float* gw = W + (size_t)(n0 + row2) * K + k0 + cf;
            uint32_t sa = sAbase + (uint32_t)buf * (TILE_F * 4) + loff;
            uint32_t sw = sWbase + (uint32_t)buf * (TILE_F * 4) + loff;
#pragma unroll
            for (int c = 0; c < 4; c++) {
                cpa16(sa + c * 16, ga + c * 4);
                cpa16(sw + c * 16, gw + c * 4);
            }
            asm volatile("cp.async.commit_group;" ::: "memory");
            asm volatile("cp.async.wait_group 2;" ::: "memory");
        } else if (p + 1 < npanels) {
            asm volatile("cp.async.wait_group 1;" ::: "memory");
        } else {
            asm volatile("cp.async.wait_group 0;" ::: "memory");
        }
        __syncthreads();

        const float* Ac = As + (p % 3) * TILE_F;
        const float* Wc = Ws + (p % 3) * TILE_F;
#pragma unroll
        for (int ks = 0; ks < 4; ks++) {
            const int cb = ks * 8 + (lane & 3);
            uint32_t a[2][4], b[4][2];
#pragma unroll
            for (int mt = 0; mt < 2; mt++) {
                int r = mwB + mt * 16 + (lane >> 2);
                a[mt][0] = __float_as_uint(Ac[r * 36 + cb]);
                a[mt][1] = __float_as_uint(Ac[(r + 8) * 36 + cb]);
                a[mt][2] = __float_as_uint(Ac[r * 36 + cb + 4]);
                a[mt][3] = __float_as_uint(Ac[(r + 8) * 36 + cb + 4]);
            }
#pragma unroll
            for (int nt = 0; nt < 4; nt++) {
                int n = nwB + nt * 8 + (lane >> 2);
                b[nt][0] = __float_as_uint(Wc[n * 36 + cb]);
                b[nt][1] = __float_as_uint(Wc[n * 36 + cb + 4]);
            }
#pragma unroll
            for (int mt = 0; mt < 2; mt++)
#pragma unroll
                for (int nt = 0; nt < 4; nt++)
                    mma_tf32(acc[mt][nt], a[mt], b[nt]);
        }
        __syncthreads();
    }

#pragma unroll
    for (int mt = 0; mt < 2; mt++) {
        int rg = m0 + mwB + mt * 16 + (lane >> 2);
#pragma unroll
        for (int nt = 0; nt < 4; nt++) {
            int c = n0 + nwB + nt * 8 + (lane & 3) * 2;
            red2(C + (size_t)rg * ldC + c,       acc[mt][nt][0], acc[mt][nt][1]);
            red2(C + (size_t)(rg + 8) * ldC + c, acc[mt][nt][2], acc[mt][nt][3]);
        }
    }
}

// ---------------- fused launch: gi0, gh0, gh1 (3 GEMMs x 4 k-splits) ----------------
__global__ __launch_bounds__(128) void gemm3_fused(const float* __restrict__ hidden,
                                                   const float* __restrict__ w_ih0,
                                                   const float* __restrict__ w_hh0,
                                                   const float* __restrict__ w_hh1) {
    int z = blockIdx.z, which = z >> 2, ks = z & 3;
    const float *Ag, *W;
    float* C;
    int K;
    if (which == 0)      { Ag = g_x;         W = w_ih0; C = g_gi;  K = E; }
    else if (which == 1) { Ag = hidden;      W = w_hh0; C = g_gh;  K = H; }
    else                 { Ag = hidden + BH; W = w_hh1; C = g_gh2; K = H; }
    int kc = K / 4;
    gemm_body(Ag, W, K, ks * kc, kc / 32, C, G, blockIdx.x * 64, blockIdx.y * 64);
}

// ---------------- single GEMM (gi1) with 4-way k-split ----------------
__global__ __launch_bounds__(128) void gemm1_ksplit(const float* __restrict__ h0,
                                                    const float* __restrict__ w_ih1) {
    int ks = blockIdx.z;
    gemm_body(h0, w_ih1, H, ks * (H / 4), (H / 4) / 32,
              g_gi1, G, blockIdx.x * 64, blockIdx.y * 64);
}

// ---------------- fused projections (8-way k-split) ----------------
__global__ __launch_bounds__(128) void proj_fused(const float* __restrict__ h1,
                                                  const float* __restrict__ t0_proj,
                                                  const float* __restrict__ t1_proj) {
    int x = blockIdx.x, ks = blockIdx.z;
    const float* W; float* C; int ld, n0;
    if (x < 4) { W = t0_proj; C = g_p0;  ld = 256; n0 = x * 64; }
    else       { W = t1_proj; C = g_p1f; ld = 64;  n0 = 0; }
    gemm_body(h1, W, H, ks * (H / 8), (H / 8) / 32,
              C, ld, n0, blockIdx.y * 64);
}

// ---------------- p1 fp32 -> bf16 (one-time; 16384 elems; 8 blocks) ----------------
__global__ void conv_p1_kernel() {
    int i = blockIdx.x * 256 + threadIdx.x;
    size_t base = (size_t)i * 8;
    float4 v0 = *(const float4*)(g_p1f + base);
    float4 v1 = *(const float4*)(g_p1f + base + 4);
    *(uint4*)(g_p1b + base) = make_uint4(
        pk2(__float2bfloat16(v0.x), __float2bfloat16(v0.y)),
        pk2(__float2bfloat16(v0.z), __float2bfloat16(v0.w)),
        pk2(__float2bfloat16(v1.x), __float2bfloat16(v1.y)),
        pk2(__float2bfloat16(v1.z), __float2bfloat16(v1.w)));
}

// ---------------- GRU gate fusion (fp32 h only) ----------------
__global__ void gates_kernel(const float* __restrict__ gi_, const float* __restrict__ gh_,
                             const float* __restrict__ b_ih, const float* __restrict__ b_hh,
                             const float* __restrict__ hprev,
                             float* __restrict__ hout) {
    int i = blockIdx.x * 256 + threadIdx.x;    // over B*H
    int m = i >> 10, j = i & 1023;
    const float* gi = gi_ + (size_t)m * G;
    const float* gh = gh_ + (size_t)m * G;
    float ir  = gi[j]         + b_ih[j];
    float iz  = gi[j + H]     + b_ih[j + H];
    float in_ = gi[j + 2 * H] + b_ih[j + 2 * H];
    float hr  = gh[j]         + b_hh[j];
    float hz  = gh[j + H]     + b_hh[j + H];
    float hn  = gh[j + 2 * H] + b_hh[j + 2 * H];
    float r = fsig(ir + hr);
    float z = fsig(iz + hz);
    float n = ftanh(in_ + r * hn);
    hout[i] = (1.f - z) * n + z * hprev[i];
}

// ---------------- head: logits[12] + log_softmax ----------------
__global__ void head_kernel(const float* __restrict__ h1, const float* __restrict__ hw) {
    __shared__ float sh[12];
    __shared__ float slse;
    int m = blockIdx.x;
    int tid = threadIdx.x, lane = tid & 31, w = tid >> 5;
    if (w < 12) {
        float s = 0.f;
        const float* hr = h1 + (size_t)m * H;
        const float* wr = hw + (size_t)w * H;
        for (int k = lane; k < H; k += 32) s += hr[k] * wr[k];
#pragma unroll
        for (int o = 16; o; o >>= 1) s += __shfl_xor_sync(0xffffffffu, s, o);
        if (lane == 0) sh[w] = s;
    }
    __syncthreads();
    if (tid == 0) {
        float mx = sh[0];
        for (int j = 1; j < 12; j++) mx = fmaxf(mx, sh[j]);
        float s = 0.f;
        for (int j = 0; j < 12; j++) s += expf(sh[j] - mx);
        slse = mx + logf(s);
    }
    __syncthreads();
    if (tid < 12) g_head[m * 12 + tid] = sh[tid] - slse;
}

// ---------------- cluster-0 (2-way) + prediction prefix cols 0..11 ----------------
__global__ void c0_kernel(const float* __restrict__ t0_out, float* __restrict__ outp) {
    __shared__ float sh[2];
    int m = blockIdx.x;
    int tid = threadIdx.x, lane = tid & 31, w = tid >> 5;
    if (w < 2) {
        float s = 0.f;
        const float* pr = g_p0 + (size_t)m * 256;
        const float* wr = t0_out + (size_t)w * 256;
        for (int k = lane; k < 256; k += 32) s += pr[k] * wr[k];
#pragma unroll
        for (int o = 16; o; o >>= 1) s += __shfl_xor_sync(0xffffffffu, s, o);
        if (lane == 0) sh[w] = s;
    }
    __syncthreads();
    if (tid < 12) {
        float* orow = outp + (size_t)m * V;
        if (tid < 10) {
            orow[tid] = g_head[m * 12 + tid];
        } else {
            float a = sh[0], b = sh[1];
            float mx = fmaxf(a, b);
            float lse = mx + logf(expf(a - mx) + expf(b - mx));
            orow[tid] = sh[tid - 10] - lse + g_head[m * 12 + 10];
        }
    }
}

// ---------------- tail GEMM [256,VT] = p1[256,64] @ t1_out[VT,64]^T (bf16) ----------------
__global__ __launch_bounds__(256) void tail_kernel(
    const float* __restrict__ Wt, float* __restrict__ outp, int pass)
{
    __shared__ __nv_bfloat16 Pb[256][72];
    __shared__ __nv_bfloat16 Wb[64][72];
    const int tid = threadIdx.x, lane = tid & 31, warp = tid >> 5;
    const int n0 = blockIdx.x * 64;
    const bool full = (n0 + 64 <= VT);

    // load P (g_p1b bf16, pre-converted): 256x64
#pragma unroll
    for (int it = 0; it < 8; it++) {
        int i = tid + it * 256;
        int row = i >> 3, c8 = (i & 7) * 8;
        *(uint4*)&Pb[row][c8] = *(const uint4*)(g_p1b + (size_t)row * 64 + c8);
    }
    // load W chunk: 64 rows x 64 cols fp32 -> bf16 (OOB rows -> 0)
#pragma unroll
    for (int it = 0; it < 4; it++) {
        int i = tid + it * 256;
        int row = i >> 4, f4 = (i & 15) * 4;
        int gidx = n0 + row;
        float4 v = make_float4(0.f, 0.f, 0.f, 0.f);
        if (gidx < VT) v = *(const float4*)(Wt + (size_t)gidx * 64 + f4);
        *(uint2*)&Wb[row][f4] = make_uint2(
            pk2(__float2bfloat16(v.x), __float2bfloat16(v.y)),
            pk2(__float2bfloat16(v.z), __float2bfloat16(v.w)));
    }
    __syncthreads();

    float acc[2][8][4];
#pragma unroll
    for (int a = 0; a < 2; a++)
#pragma unroll
        for (int b = 0; b < 8; b++)
#pragma unroll
            for (int c = 0; c < 4; c++) acc[a][b][c] = 0.f;

#pragma unroll
    for (int ks = 0; ks < 4; ks++) {
        const int cb = ks * 16 + (lane & 3) * 2;
        uint32_t a[2][4], b[8][2];
#pragma unroll
        for (int mt = 0; mt < 2; mt++) {
            int r = warp * 32 + mt * 16 + (lane >> 2);
            a[mt][0] = *(const uint32_t*)&Pb[r][cb];
            a[mt][1] = *(const uint32_t*)&Pb[r + 8][cb];
            a[mt][2] = *(const uint32_t*)&Pb[r][cb + 8];
            a[mt][3] = *(const uint32_t*)&Pb[r + 8][cb + 8];
        }
#pragma unroll
        for (int nt = 0; nt < 8; nt++) {
            int n = nt * 8 + (lane >> 2);
            b[nt][0] = *(const uint32_t*)&Wb[n][cb];
            b[nt][1] = *(const uint32_t*)&Wb[n][cb + 8];
        }
#pragma unroll
        for (int mt = 0; mt < 2; mt++)
#pragma unroll
            for (int nt = 0; nt < 8; nt++)
                mma16816(acc[mt][nt], a[mt], b[nt]);
    }

    if (pass == 0) {
#pragma unroll
        for (int j = 0; j < 4; j++) {
            int mt = j >> 1, hf = j & 1;
            int r = warp * 32 + (lane >> 2) + hf * 8 + mt * 16;
            float ss = 0.f;
            if (full) {
#pragma unroll
                for (int nt = 0; nt < 8; nt++) {
                    ss += ex2f_(LOG2E * acc[mt][nt][hf * 2]);
                    ss += ex2f_(LOG2E * acc[mt][nt][hf * 2 + 1]);
                }
            } else {
#pragma unroll
                for (int nt = 0; nt < 8; nt++)
#pragma unroll
                    for (int e = 0; e < 2; e++) {
                        int gcol = n0 + nt * 8 + (lane & 3) * 2 + e;
                        if (gcol < VT) ss += ex2f_(LOG2E * acc[mt][nt][hf * 2 + e]);
                    }
            }
            ss += __shfl_xor_sync(0xffffffffu, ss, 1);
            ss += __shfl_xor_sync(0xffffffffu, ss, 2);
            if ((lane & 3) == 0)
                g_psum[(size_t)r * TSTRIDE + blockIdx.x] = ss;
        }
    } else {
#pragma unroll
        for (int j = 0; j < 4; j++) {
            int mt = j >> 1, hf = j & 1;
            int r = warp * 32 + (lane >> 2) + hf * 8 + mt * 16;
            float ofs = g_off[r];
            float* orow = outp + (size_t)r * V + 12;
#pragma unroll
            for (int nt = 0; nt < 8; nt++) {
                int c = n0 + nt * 8 + (lane & 3) * 2;
                float v0 = acc[mt][nt][hf * 2] + ofs;
                float v1 = acc[mt][nt][hf * 2 + 1] + ofs;
                if (full) {
                    *(float2*)(orow + c) = make_float2(v0, v1);
                } else {
                    if (c < VT)     orow[c] = v0;
                    if (c + 1 < VT) orow[c + 1] = v1;
                }
            }
        }
    }
}

// ---------------- combine tail partial sums into per-row offset ----------------
__global__ void combine_kernel() {
    int m = blockIdx.x;
    int tid = threadIdx.x;
    float s = 0.f;
    for (int b = tid; b < TNB; b += 256)
        s += g_psum[(size_t)m * TSTRIDE + b];
    __shared__ float sh[256];
    sh[tid] = s;
    __syncthreads();
    for (int o = 128; o; o >>= 1) {
        if (tid < o) sh[tid] += sh[tid + o];
        __syncthreads();
    }
    if (tid == 0) g_off[m] = g_head[m * 12 + 11] - logf(sh[0]);
}

// ---------------- launch ----------------
extern "C" void kernel_launch(void* const* d_in, const int* in_sizes, int n_in,
                              void* d_out, int out_size) {
    const int*   input  = (const int*)  d_in[0];
    const float* hidden = (const float*)d_in[1];
    // d_in[2] = start_state (unused by reference)
    const float* emb    = (const float*)d_in[3];
    const float* w_ih0  = (const float*)d_in[4];
    const float* w_hh0  = (const float*)d_in[5];
    const float* b_ih0  = (const float*)d_in[6];
    const float* b_hh0  = (const float*)d_in[7];
    const float* w_ih1  = (const float*)d_in[8];
    const float* w_hh1  = (const float*)d_in[9];
    const float* b_ih1  = (const float*)d_in[10];
    const float* b_hh1  = (const float*)d_in[11];
    const float* head_w = (const float*)d_in[12];
    const float* t0_proj= (const float*)d_in[13];
    const float* t0_out = (const float*)d_in[14];
    const float* t1_proj= (const float*)d_in[15];
    const float* t1_out = (const float*)d_in[16];
    float* out = (float*)d_out;

    cudaFuncSetAttribute(gemm3_fused,  cudaFuncAttributeMaxDynamicSharedMemorySize, SMEM_GEMM);
    cudaFuncSetAttribute(gemm1_ksplit, cudaFuncAttributeMaxDynamicSharedMemorySize, SMEM_GEMM);
    cudaFuncSetAttribute(proj_fused,   cudaFuncAttributeMaxDynamicSharedMemorySize, SMEM_GEMM);

    float *pgi, *pgh, *pgh2, *pgi1, *ph0b, *ph1b;
    cudaGetSymbolAddress((void**)&pgi,  g_gi);
    cudaGetSymbolAddress((void**)&pgh,  g_gh);
    cudaGetSymbolAddress((void**)&pgh2, g_gh2);
    cudaGetSymbolAddress((void**)&pgi1, g_gi1);
    cudaGetSymbolAddress((void**)&ph0b, g_h0buf);
    cudaGetSymbolAddress((void**)&ph1b, g_h1buf);

    bool has_hidden = (out_size >= BV + 2 * BH);
    float* h0 = has_hidden ? out + (size_t)BV : ph0b;
    float* h1 = has_hidden ? out + (size_t)BV + BH : ph1b;

    // 0: gather x (fp32) + zero accumulators
    prep_kernel<<<PREP_BLOCKS, 256>>>(input, emb);
    // 1: gi0, gh0, gh1 fused (tf32, 3 GEMMs x 4 k-splits, 2304 blocks)
    gemm3_fused<<<dim3(48, 4, 12), 128, SMEM_GEMM>>>(hidden, w_ih0, w_hh0, w_hh1);
    // 2: gates layer 0 -> h0
    gates_kernel<<<BH / 256, 256>>>(pgi, pgh, b_ih0, b_hh0, hidden, h0);
    // 3: gi1 = h0 @ w_ih1^T (tf32, 4-way k-split, 768 blocks)
    gemm1_ksplit<<<dim3(48, 4, 4), 128, SMEM_GEMM>>>(h0, w_ih1);
    // 4: gates layer 1 -> h1
    gates_kernel<<<BH / 256, 256>>>(pgi1, pgh2, b_ih1, b_hh1, hidden + BH, h1);
    // 5: p0/p1 projections fused (tf32, 8-way k-split)
    proj_fused<<<dim3(5, 4, 8), 128, SMEM_GEMM>>>(h1, t0_proj, t1_proj);
    // 6: p1 fp32 -> bf16 (tiny one-time convert)
    conv_p1_kernel<<<(B * 64 / 8) / 256, 256>>>();
    // 7: head log-softmax
    head_kernel<<<B, 384>>>(h1, head_w);
    // 8: cluster 0 + output prefix
    c0_kernel<<<B, 64>>>(t0_out, out);
    // 9: tail pass 0 (sumexp partials)
    tail_kernel<<<TNB, 256>>>(t1_out, out, 0);
    // 10: combine -> per-row offset
    combine_kernel<<<B, 256>>>();
    // 11: tail pass 1 (write log-probs)
    tail_kernel<<<TNB, 256>>>(t1_out, out, 1);
}

// round 15
// speedup vs baseline: 1.0100x; 1.0100x over previous
#include <cuda_runtime.h>
#include <cuda_bf16.h>
#include <cstdint>

#define B 256
#define E 512
#define H 1024
#define G 3072          // 3*H
#define V 128000
#define VT 127988       // V - 12
#define BV (B*V)
#define BH (B*H)
#define TNB2 1000       // tail blocks (BN=128)
#define TSTRIDE 2048
#define LOG2E 1.4426950408889634f

// ---------------- scratch (device globals; no allocations allowed) ----------------
__device__ __align__(16) float g_x[B*E];        // gathered embedding (fp32)
__device__ __align__(16) float g_gi[B*G];       // gi0 accumulator
__device__ __align__(16) float g_gh[B*G];       // gh0 accumulator
__device__ __align__(16) float g_gh2[B*G];      // gh1 accumulator
__device__ __align__(16) float g_gi1[B*G];      // gi1 accumulator
__device__ __align__(16) float g_p0[B*256];
__device__ __align__(16) float g_p1f[B*64];
__device__ __align__(16) __nv_bfloat16 g_p1b[B*64];
__device__ float g_head[B*12];      // log-softmaxed head
__device__ float g_off[B];          // head_lp[:,11] - lse_tail
__device__ float g_psum[B*TSTRIDE];
__device__ float g_h0buf[BH], g_h1buf[BH];   // fallback if d_out lacks hidden region

// ---------------- helpers ----------------
__device__ __forceinline__ void mma16816(float* d, const uint32_t* a, const uint32_t* b) {
    asm volatile(
        "mma.sync.aligned.m16n8k16.row.col.f32.bf16.bf16.f32 "
        "{%0,%1,%2,%3}, {%4,%5,%6,%7}, {%8,%9}, {%0,%1,%2,%3};\n"
        : "+f"(d[0]), "+f"(d[1]), "+f"(d[2]), "+f"(d[3])
        : "r"(a[0]), "r"(a[1]), "r"(a[2]), "r"(a[3]), "r"(b[0]), "r"(b[1]));
}

// tf32 MMA: operands are fp32 bit patterns (HW uses top 19 bits)
__device__ __forceinline__ void mma_tf32(float* d, const uint32_t* a, const uint32_t* b) {
    asm volatile(
        "mma.sync.aligned.m16n8k8.row.col.f32.tf32.tf32.f32 "
        "{%0,%1,%2,%3}, {%4,%5,%6,%7}, {%8,%9}, {%0,%1,%2,%3};\n"
        : "+f"(d[0]), "+f"(d[1]), "+f"(d[2]), "+f"(d[3])
        : "r"(a[0]), "r"(a[1]), "r"(a[2]), "r"(a[3]), "r"(b[0]), "r"(b[1]));
}

__device__ __forceinline__ void red2(float* p, float a, float b) {
    asm volatile("red.global.add.v2.f32 [%0], {%1, %2};" :: "l"(p), "f"(a), "f"(b) : "memory");
}

__device__ __forceinline__ uint32_t pk2(__nv_bfloat16 a, __nv_bfloat16 b) {
    __nv_bfloat162 t; t.x = a; t.y = b;
    return *(uint32_t*)&t;
}

__device__ __forceinline__ float ex2f_(float x) {
    float y; asm("ex2.approx.ftz.f32 %0, %1;" : "=f"(y) : "f"(x)); return y;
}
__device__ __forceinline__ float rcpf_(float x) {
    float y; asm("rcp.approx.ftz.f32 %0, %1;" : "=f"(y) : "f"(x)); return y;
}
__device__ __forceinline__ float fsig(float x)  { return rcpf_(1.f + ex2f_(-LOG2E * x)); }
__device__ __forceinline__ float ftanh(float x) { return 2.f * rcpf_(1.f + ex2f_(-2.f * LOG2E * x)) - 1.f; }

__device__ __forceinline__ uint32_t smem_u32(const void* p) {
    uint32_t a;
    asm("{ .reg .u64 t; cvta.to.shared.u64 t, %1; cvt.u32.u64 %0, t; }" : "=r"(a) : "l"(p));
    return a;
}
__device__ __forceinline__ void cpa16(uint32_t s, const void* g) {
    asm volatile("cp.async.cg.shared.global [%0], [%1], 16;" :: "r"(s), "l"(g) : "memory");
}

// ---------------- prep: gather x (fp32) + zero all GEMM accumulators ----------------
#define NXF4    (B*E/4)                              // 32768
#define NGF4    (B*G/4)                              // 196608 per gate buffer
#define ZERO_F4 (4*NGF4 + B*256/4 + B*64/4)          // 806912
#define PREP_BLOCKS ((NXF4 + ZERO_F4) / 256)         // 3280 exactly

__global__ void prep_kernel(const int* __restrict__ idx, const float* __restrict__ emb) {
    int i = blockIdx.x * 256 + threadIdx.x;
    if (i < NXF4) {
        int row = i >> 7;                            // E/4 = 128
        int c4  = (i & 127) * 4;
        float4 v = *(const float4*)(emb + (size_t)idx[row] * E + c4);
        *(float4*)(g_x + (size_t)row * E + c4) = v;
        return;
    }
    int j = i - NXF4;
    float4 z = make_float4(0.f, 0.f, 0.f, 0.f);
    if      (j < 1*NGF4) ((float4*)g_gi )[j]          = z;
    else if (j < 2*NGF4) ((float4*)g_gh )[j - 1*NGF4] = z;
    else if (j < 3*NGF4) ((float4*)g_gh2)[j - 2*NGF4] = z;
    else if (j < 4*NGF4) ((float4*)g_gi1)[j - 3*NGF4] = z;
    else if (j < 4*NGF4 + B*256/4) ((float4*)g_p0)[j - 4*NGF4] = z;
    else                 ((float4*)g_p1f)[j - 4*NGF4 - B*256/4] = z;
}

// ---------------- TF32 GEMM body: BM=64, BN=128, BK=32, 256 threads ----------------
// 8 warps (2m x 4n), warp tile 32x32. 2-stage cp.async. nmax masks the N range.
// C[m0:m0+64, n0:n0+min(128,nmax-n0)] += A @ W^T (red.global output)
#define TILE_A (64 * 36)               // floats
#define TILE_W (128 * 36)
#define STAGE_F (TILE_A + TILE_W)      // 6912 floats = 27648 B
#define SMEM_GEMM (2 * STAGE_F * 4)    // 55296 B

__device__ __forceinline__ void gemm_body(
    const float* __restrict__ A,
    const float* __restrict__ W, int K, int k0s, int npanels,
    float* __restrict__ C, int ldC, int n0, int m0, int nmax)
{
    extern __shared__ float dsm[];
    const int tid = threadIdx.x, lane = tid & 31, warp = tid >> 5;
    const int mwB = (warp & 1) * 32;
    const int nwB = (warp >> 1) * 32;

    const int wrow = tid >> 1;            // 0..127  W load row
    const int wcf  = (tid & 1) * 16;
    const int arow = (tid & 127) >> 1;    // 0..63   A load row (tid<128)

    float acc[2][4][4];
#pragma unroll
    for (int a = 0; a < 2; a++)
#pragma unroll
        for (int b = 0; b < 4; b++)
#pragma unroll
            for (int c = 0; c < 4; c++) acc[a][b][c] = 0.f;

    // issue panel p into stage p&1
    // (lambda-free: duplicated inline below)
    {
        int k0 = k0s;
        float* S = dsm;
        int gr = n0 + wrow; if (gr >= nmax) gr = nmax - 1;
        const float* gw = W + (size_t)gr * K + k0 + wcf;
        uint32_t sw = smem_u32(S + TILE_A + wrow * 36 + wcf);
#pragma unroll
        for (int c = 0; c < 4; c++) cpa16(sw + c * 16, gw + c * 4);
        if (tid < 128) {
            const float* ga = A + (size_t)(m0 + arow) * K + k0 + wcf;
            uint32_t sa = smem_u32(S + arow * 36 + wcf);
#pragma unroll
            for (int c = 0; c < 4; c++) cpa16(sa + c * 16, ga + c * 4);
        }
        asm volatile("cp.async.commit_group;" ::: "memory");
    }

    for (int p = 0; p < npanels; p++) {
        if (p + 1 < npanels) {
            int k0 = k0s + (p + 1) * 32;
            float* S = dsm + ((p + 1) & 1) * STAGE_F;
            int gr = n0 + wrow; if (gr >= nmax) gr = nmax - 1;
            const float* gw = W + (size_t)gr * K + k0 + wcf;
            uint32_t sw = smem_u32(S + TILE_A + wrow * 36 + wcf);
#pragma unroll
            for (int c = 0; c < 4; c++) cpa16(sw + c * 16, gw + c * 4);
            if (tid < 128) {
                const float* ga = A + (size_t)(m0 + arow) * K + k0 + wcf;
                uint32_t sa = smem_u32(S + arow * 36 + wcf);
#pragma unroll
                for (int c = 0; c < 4; c++) cpa16(sa + c * 16, ga + c * 4);
            }
            asm volatile("cp.async.commit_group;" ::: "memory");
            asm volatile("cp.async.wait_group 1;" ::: "memory");
        } else {
            asm volatile("cp.async.wait_group 0;" ::: "memory");
        }
        __syncthreads();

        const float* Ac = dsm + (p & 1) * STAGE_F;
        const float* Wc = Ac + TILE_A;
#pragma unroll
        for (int ks = 0; ks < 4; ks++) {
            const int cb = ks * 8 + (lane & 3);
            uint32_t a[2][4], b[4][2];
#pragma unroll
            for (int mt = 0; mt < 2; mt++) {
                int r = mwB + mt * 16 + (lane >> 2);
                a[mt][0] = __float_as_uint(Ac[r * 36 + cb]);
                a[mt][1] = __float_as_uint(Ac[(r + 8) * 36 + cb]);
                a[mt][2] = __float_as_uint(Ac[r * 36 + cb + 4]);
                a[mt][3] = __float_as_uint(Ac[(r + 8) * 36 + cb + 4]);
            }
#pragma unroll
            for (int nt = 0; nt < 4; nt++) {
                int n = nwB + nt * 8 + (lane >> 2);
                b[nt][0] = __float_as_uint(Wc[n * 36 + cb]);
                b[nt][1] = __float_as_uint(Wc[n * 36 + cb + 4]);
            }
#pragma unroll
            for (int mt = 0; mt < 2; mt++)
#pragma unroll
                for (int nt = 0; nt < 4; nt++)
                    mma_tf32(acc[mt][nt], a[mt], b[nt]);
        }
        __syncthreads();
    }

#pragma unroll
    for (int mt = 0; mt < 2; mt++) {
        int rg = m0 + mwB + mt * 16 + (lane >> 2);
#pragma unroll
        for (int nt = 0; nt < 4; nt++) {
            int c = n0 + nwB + nt * 8 + (lane & 3) * 2;
            if (c < nmax) {
                red2(C + (size_t)rg * ldC + c,       acc[mt][nt][0], acc[mt][nt][1]);
                red2(C + (size_t)(rg + 8) * ldC + c, acc[mt][nt][2], acc[mt][nt][3]);
            }
        }
    }
}

// ---------------- fused launch: gi0, gh0, gh1 (3 GEMMs x 4 k-splits) ----------------
__global__ __launch_bounds__(256) void gemm3_fused(const float* __restrict__ hidden,
                                                   const float* __restrict__ w_ih0,
                                                   const float* __restrict__ w_hh0,
                                                   const float* __restrict__ w_hh1) {
    int z = blockIdx.z, which = z >> 2, ks = z & 3;
    const float *Ag, *W;
    float* C;
    int K;
    if (which == 0)      { Ag = g_x;         W = w_ih0; C = g_gi;  K = E; }
    else if (which == 1) { Ag = hidden;      W = w_hh0; C = g_gh;  K = H; }
    else                 { Ag = hidden + BH; W = w_hh1; C = g_gh2; K = H; }
    int kc = K / 4;
    gemm_body(Ag, W, K, ks * kc, kc / 32, C, G, blockIdx.x * 128, blockIdx.y * 64, G);
}

// ---------------- single GEMM (gi1) with 4-way k-split ----------------
__global__ __launch_bounds__(256) void gemm1_ksplit(const float* __restrict__ h0,
                                                    const float* __restrict__ w_ih1) {
    int ks = blockIdx.z;
    gemm_body(h0, w_ih1, H, ks * (H / 4), (H / 4) / 32,
              g_gi1, G, blockIdx.x * 128, blockIdx.y * 64, G);
}

// ---------------- fused projections (8-way k-split) ----------------
__global__ __launch_bounds__(256) void proj_fused(const float* __restrict__ h1,
                                                  const float* __restrict__ t0_proj,
                                                  const float* __restrict__ t1_proj) {
    int x = blockIdx.x, ks = blockIdx.z;
    if (x < 2) {
        gemm_body(h1, t0_proj, H, ks * (H / 8), (H / 8) / 32,
                  g_p0, 256, x * 128, blockIdx.y * 64, 256);
    } else {
        gemm_body(h1, t1_proj, H, ks * (H / 8), (H / 8) / 32,
                  g_p1f, 64, 0, blockIdx.y * 64, 64);
    }
}

// ---------------- p1 fp32 -> bf16 (one-time; 16384 elems; 8 blocks) ----------------
__global__ void conv_p1_kernel() {
    int i = blockIdx.x * 256 + threadIdx.x;
    size_t base = (size_t)i * 8;
    float4 v0 = *(const float4*)(g_p1f + base);
    float4 v1 = *(const float4*)(g_p1f + base + 4);
    *(uint4*)(g_p1b + base) = make_uint4(
        pk2(__float2bfloat16(v0.x), __float2bfloat16(v0.y)),
        pk2(__float2bfloat16(v0.z), __float2bfloat16(v0.w)),
        pk2(__float2bfloat16(v1.x), __float2bfloat16(v1.y)),
        pk2(__float2bfloat16(v1.z), __float2bfloat16(v1.w)));
}

// ---------------- GRU gate fusion ----------------
__global__ void gates_kernel(const float* __restrict__ gi_, const float* __restrict__ gh_,
                             const float* __restrict__ b_ih, const float* __restrict__ b_hh,
                             const float* __restrict__ hprev,
                             float* __restrict__ hout) {
    int i = blockIdx.x * 256 + threadIdx.x;    // over B*H
    int m = i >> 10, j = i & 1023;
    const float* gi = gi_ + (size_t)m * G;
    const float* gh = gh_ + (size_t)m * G;
    float ir  = gi[j]         + b_ih[j];
    float iz  = gi[j + H]     + b_ih[j + H];
    float in_ = gi[j + 2 * H] + b_ih[j + 2 * H];
    float hr  = gh[j]         + b_hh[j];
    float hz  = gh[j + H]     + b_hh[j + H];
    float hn  = gh[j + 2 * H] + b_hh[j + 2 * H];
    float r = fsig(ir + hr);
    float z = fsig(iz + hz);
    float n = ftanh(in_ + r * hn);
    hout[i] = (1.f - z) * n + z * hprev[i];
}

// ---------------- head: logits[12] + log_softmax ----------------
__global__ void head_kernel(const float* __restrict__ h1, const float* __restrict__ hw) {
    __shared__ float sh[12];
    __shared__ float slse;
    int m = blockIdx.x;
    int tid = threadIdx.x, lane = tid & 31, w = tid >> 5;
    if (w < 12) {
        float s = 0.f;
        const float* hr = h1 + (size_t)m * H;
        const float* wr = hw + (size_t)w * H;
        for (int k = lane; k < H; k += 32) s += hr[k] * wr[k];
#pragma unroll
        for (int o = 16; o; o >>= 1) s += __shfl_xor_sync(0xffffffffu, s, o);
        if (lane == 0) sh[w] = s;
    }
    __syncthreads();
    if (tid == 0) {
        float mx = sh[0];
        for (int j = 1; j < 12; j++) mx = fmaxf(mx, sh[j]);
        float s = 0.f;
        for (int j = 0; j < 12; j++) s += expf(sh[j] - mx);
        slse = mx + logf(s);
    }
    __syncthreads();
    if (tid < 12) g_head[m * 12 + tid] = sh[tid] - slse;
}

// ---------------- cluster-0 (2-way) + prediction prefix cols 0..11 ----------------
__global__ void c0_kernel(const float* __restrict__ t0_out, float* __restrict__ outp) {
    __shared__ float sh[2];
    int m = blockIdx.x;
    int tid = threadIdx.x, lane = tid & 31, w = tid >> 5;
    if (w < 2) {
        float s = 0.f;
        const float* pr = g_p0 + (size_t)m * 256;
        const float* wr = t0_out + (size_t)w * 256;
        for (int k = lane; k < 256; k += 32) s += pr[k] * wr[k];
#pragma unroll
        for (int o = 16; o; o >>= 1) s += __shfl_xor_sync(0xffffffffu, s, o);
        if (lane == 0) sh[w] = s;
    }
    __syncthreads();
    if (tid < 12) {
        float* orow = outp + (size_t)m * V;
        if (tid < 10) {
            orow[tid] = g_head[m * 12 + tid];
        } else {
            float a = sh[0], b = sh[1];
            float mx = fmaxf(a, b);
            float lse = mx + logf(expf(a - mx) + expf(b - mx));
            orow[tid] = sh[tid - 10] - lse + g_head[m * 12 + 10];
        }
    }
}

// ---------------- tail GEMM [256,VT] = p1 @ t1_out^T, BN=128, 512 threads ----------------
// 16 warps as 8m x 2n: warp covers rows (warp>>1)*32..+32, cols (warp&1)*64..+64.
// smem (dynamic): Pb 256x72 bf16 (36864B) + Wb 128x72 bf16 (18432B) = 55296B.
#define SMEM_TAIL 55296

__global__ __launch_bounds__(512) void tail_kernel(
    const float* __restrict__ Wt, float* __restrict__ outp, int pass)
{
    extern __shared__ __nv_bfloat16 tsm[];
    __nv_bfloat16* Pb = tsm;              // [256][72]
    __nv_bfloat16* Wb = tsm + 256 * 72;   // [128][72]
    const int tid = threadIdx.x, lane = tid & 31, warp = tid >> 5;
    const int wm = warp >> 1;             // 0..7  row group
    const int wn = warp & 1;              // 0..1  col half
    const int n0 = blockIdx.x * 128;
    const bool full = (n0 + 128 <= VT);

    // load P (g_p1b bf16): 256x64 = 2048 uint4, 4 per thread
#pragma unroll
    for (int it = 0; it < 4; it++) {
        int i = tid + it * 512;
        int row = i >> 3, c8 = (i & 7) * 8;
        *(uint4*)&Pb[row * 72 + c8] = *(const uint4*)(g_p1b + (size_t)row * 64 + c8);
    }
    // load W chunk: 128 rows x 64 cols fp32 -> bf16 (OOB rows -> 0): 2048 float4
#pragma unroll
    for (int it = 0; it < 4; it++) {
        int i = tid + it * 512;
        int row = i >> 4, f4 = (i & 15) * 4;
        int gidx = n0 + row;
        float4 v = make_float4(0.f, 0.f, 0.f, 0.f);
        if (gidx < VT) v = *(const float4*)(Wt + (size_t)gidx * 64 + f4);
        *(uint2*)&Wb[row * 72 + f4] = make_uint2(
            pk2(__float2bfloat16(v.x), __float2bfloat16(v.y)),
            pk2(__float2bfloat16(v.z), __float2bfloat16(v.w)));
    }
    __syncthreads();

    float acc[2][8][4];
#pragma unroll
    for (int a = 0; a < 2; a++)
#pragma unroll
        for (int b = 0; b < 8; b++)
#pragma unroll
            for (int c = 0; c < 4; c++) acc[a][b][c] = 0.f;

#pragma unroll
    for (int ks = 0; ks < 4; ks++) {
        const int cb = ks * 16 + (lane & 3) * 2;
        uint32_t a[2][4], b[8][2];
#pragma unroll
        for (int mt = 0; mt < 2; mt++) {
            int r = wm * 32 + mt * 16 + (lane >> 2);
            a[mt][0] = *(const uint32_t*)&Pb[r * 72 + cb];
            a[mt][1] = *(const uint32_t*)&Pb[(r + 8) * 72 + cb];
            a[mt][2] = *(const uint32_t*)&Pb[r * 72 + cb + 8];
            a[mt][3] = *(const uint32_t*)&Pb[(r + 8) * 72 + cb + 8];
        }
#pragma unroll
        for (int nt = 0; nt < 8; nt++) {
            int n = wn * 64 + nt * 8 + (lane >> 2);
            b[nt][0] = *(const uint32_t*)&Wb[n * 72 + cb];
            b[nt][1] = *(const uint32_t*)&Wb[n * 72 + cb + 8];
        }
#pragma unroll
        for (int mt = 0; mt < 2; mt++)
#pragma unroll
            for (int nt = 0; nt < 8; nt++)
                mma16816(acc[mt][nt], a[mt], b[nt]);
    }

    if (pass == 0) {
#pragma unroll
        for (int j = 0; j < 4; j++) {
            int mt = j >> 1, hf = j & 1;
            int r = wm * 32 + (lane >> 2) + hf * 8 + mt * 16;
            float ss = 0.f;
            if (full) {
#pragma unroll
                for (int nt = 0; nt < 8; nt++) {
                    ss += ex2f_(LOG2E * acc[mt][nt][hf * 2]);
                    ss += ex2f_(LOG2E * acc[mt][nt][hf * 2 + 1]);
                }
            } else {
#pragma unroll
                for (int nt = 0; nt < 8; nt++)
#pragma unroll
                    for (int e = 0; e < 2; e++) {
                        int gcol = n0 + wn * 64 + nt * 8 + (lane & 3) * 2 + e;
                        if (gcol < VT) ss += ex2f_(LOG2E * acc[mt][nt][hf * 2 + e]);
                    }
            }
            ss += __shfl_xor_sync(0xffffffffu, ss, 1);
            ss += __shfl_xor_sync(0xffffffffu, ss, 2);
            if ((lane & 3) == 0)
                g_psum[(size_t)r * TSTRIDE + blockIdx.x * 2 + wn] = ss;
        }
    } else {
#pragma unroll
        for (int j = 0; j < 4; j++) {
            int mt = j >> 1, hf = j & 1;
            int r = wm * 32 + (lane >> 2) + hf * 8 + mt * 16;
            float ofs = g_off[r];
            float* orow = outp + (size_t)r * V + 12;
#pragma unroll
            for (int nt = 0; nt < 8; nt++) {
                int c = n0 + wn * 64 + nt * 8 + (lane & 3) * 2;
                float v0 = acc[mt][nt][hf * 2] + ofs;
                float v1 = acc[mt][nt][hf * 2 + 1] + ofs;
                if (full) {
                    *(float2*)(orow + c) = make_float2(v0, v1);
                } else {
                    if (c < VT)     orow[c] = v0;
                    if (c + 1 < VT) orow[c + 1] = v1;
                }
            }
        }
    }
}

// ---------------- combine tail partial sums into per-row offset ----------------
__global__ void combine_kernel() {
    int m = blockIdx.x;
    int tid = threadIdx.x;
    float s = 0.f;
    for (int b = tid; b < TNB2 * 2; b += 256)
        s += g_psum[(size_t)m * TSTRIDE + b];
    __shared__ float sh[256];
    sh[tid] = s;
    __syncthreads();
    for (int o = 128; o; o >>= 1) {
        if (tid < o) sh[tid] += sh[tid + o];
        __syncthreads();
    }
    if (tid == 0) g_off[m] = g_head[m * 12 + 11] - logf(sh[0]);
}

// ---------------- launch ----------------
extern "C" void kernel_launch(void* const* d_in, const int* in_sizes, int n_in,
                              void* d_out, int out_size) {
    const int*   input  = (const int*)  d_in[0];
    const float* hidden = (const float*)d_in[1];
    // d_in[2] = start_state (unused by reference)
    const float* emb    = (const float*)d_in[3];
    const float* w_ih0  = (const float*)d_in[4];
    const float* w_hh0  = (const float*)d_in[5];
    const float* b_ih0  = (const float*)d_in[6];
    const float* b_hh0  = (const float*)d_in[7];
    const float* w_ih1  = (const float*)d_in[8];
    const float* w_hh1  = (const float*)d_in[9];
    const float* b_ih1  = (const float*)d_in[10];
    const float* b_hh1  = (const float*)d_in[11];
    const float* head_w = (const float*)d_in[12];
    const float* t0_proj= (const float*)d_in[13];
    const float* t0_out = (const float*)d_in[14];
    const float* t1_proj= (const float*)d_in[15];
    const float* t1_out = (const float*)d_in[16];
    float* out = (float*)d_out;

    cudaFuncSetAttribute(gemm3_fused,  cudaFuncAttributeMaxDynamicSharedMemorySize, SMEM_GEMM);
    cudaFuncSetAttribute(gemm1_ksplit, cudaFuncAttributeMaxDynamicSharedMemorySize, SMEM_GEMM);
    cudaFuncSetAttribute(proj_fused,   cudaFuncAttributeMaxDynamicSharedMemorySize, SMEM_GEMM);
    cudaFuncSetAttribute(tail_kernel,  cudaFuncAttributeMaxDynamicSharedMemorySize, SMEM_TAIL);

    float *pgi, *pgh, *pgh2, *pgi1, *ph0b, *ph1b;
    cudaGetSymbolAddress((void**)&pgi,  g_gi);
    cudaGetSymbolAddress((void**)&pgh,  g_gh);
    cudaGetSymbolAddress((void**)&pgh2, g_gh2);
    cudaGetSymbolAddress((void**)&pgi1, g_gi1);
    cudaGetSymbolAddress((void**)&ph0b, g_h0buf);
    cudaGetSymbolAddress((void**)&ph1b, g_h1buf);

    bool has_hidden = (out_size >= BV + 2 * BH);
    float* h0 = has_hidden ? out + (size_t)BV : ph0b;
    float* h1 = has_hidden ? out + (size_t)BV + BH : ph1b;

    // 0: gather x (fp32) + zero accumulators
    prep_kernel<<<PREP_BLOCKS, 256>>>(input, emb);
    // 1: gi0, gh0, gh1 fused (tf32, BN=128, 3 GEMMs x 4 k-splits, 1152 blocks)
    gemm3_fused<<<dim3(24, 4, 12), 256, SMEM_GEMM>>>(hidden, w_ih0, w_hh0, w_hh1);
    // 2: gates layer 0 -> h0
    gates_kernel<<<BH / 256, 256>>>(pgi, pgh, b_ih0, b_hh0, hidden, h0);
    // 3: gi1 = h0 @ w_ih1^T (tf32, 4-way k-split, 384 blocks)
    gemm1_ksplit<<<dim3(24, 4, 4), 256, SMEM_GEMM>>>(h0, w_ih1);
    // 4: gates layer 1 -> h1
    gates_kernel<<<BH / 256, 256>>>(pgi1, pgh2, b_ih1, b_hh1, hidden + BH, h1);
    // 5: p0/p1 projections fused (tf32, 8-way k-split, 96 blocks)
    proj_fused<<<dim3(3, 4, 8), 256, SMEM_GEMM>>>(h1, t0_proj, t1_proj);
    // 6: p1 fp32 -> bf16 (tiny one-time convert)
    conv_p1_kernel<<<(B * 64 / 8) / 256, 256>>>();
    // 7: head log-softmax
    head_kernel<<<B, 384>>>(h1, head_w);
    // 8: cluster 0 + output prefix
    c0_kernel<<<B, 64>>>(t0_out, out);
    // 9: tail pass 0 (sumexp partials, BN=128, 1000 blocks)
    tail_kernel<<<TNB2, 512, SMEM_TAIL>>>(t1_out, out, 0);
    // 10: combine -> per-row offset
    combine_kernel<<<B, 256>>>();
    // 11: tail pass 1 (write log-probs)
    tail_kernel<<<TNB2, 512, SMEM_TAIL>>>(t1_out, out, 1);
}

// round 16
// speedup vs baseline: 1.0747x; 1.0640x over previous
#include <cuda_runtime.h>
#include <cuda_bf16.h>
#include <cstdint>

#define B 256
#define E 512
#define H 1024
#define G 3072          // 3*H
#define V 128000
#define VT 127988       // V - 12
#define BV (B*V)
#define BH (B*H)
#define TNB 2000        // tail blocks (BN=64)
#define TSTRIDE 2048
#define LOG2E 1.4426950408889634f

// ---------------- scratch (device globals; no allocations allowed) ----------------
__device__ __align__(16) float g_x[B*E];        // gathered embedding (fp32)
__device__ __align__(16) float g_gi[B*G];       // gi0 accumulator
__device__ __align__(16) float g_gh[B*G];       // gh0 accumulator
__device__ __align__(16) float g_gh2[B*G];      // gh1 accumulator
__device__ __align__(16) float g_gi1[B*G];      // gi1 accumulator
__device__ __align__(16) float g_p0[B*256];
__device__ __align__(16) float g_p1f[B*64];
__device__ __align__(16) __nv_bfloat16 g_p1b[B*64];
__device__ float g_head[B*12];      // log-softmaxed head
__device__ float g_off[B];          // head_lp[:,11] - lse_tail
__device__ float g_psum[B*TSTRIDE];
__device__ float g_h0buf[BH], g_h1buf[BH];   // fallback if d_out lacks hidden region

// ---------------- helpers ----------------
__device__ __forceinline__ void mma16816(float* d, const uint32_t* a, const uint32_t* b) {
    asm volatile(
        "mma.sync.aligned.m16n8k16.row.col.f32.bf16.bf16.f32 "
        "{%0,%1,%2,%3}, {%4,%5,%6,%7}, {%8,%9}, {%0,%1,%2,%3};\n"
        : "+f"(d[0]), "+f"(d[1]), "+f"(d[2]), "+f"(d[3])
        : "r"(a[0]), "r"(a[1]), "r"(a[2]), "r"(a[3]), "r"(b[0]), "r"(b[1]));
}

// tf32 MMA: operands are fp32 bit patterns (HW uses top 19 bits)
__device__ __forceinline__ void mma_tf32(float* d, const uint32_t* a, const uint32_t* b) {
    asm volatile(
        "mma.sync.aligned.m16n8k8.row.col.f32.tf32.tf32.f32 "
        "{%0,%1,%2,%3}, {%4,%5,%6,%7}, {%8,%9}, {%0,%1,%2,%3};\n"
        : "+f"(d[0]), "+f"(d[1]), "+f"(d[2]), "+f"(d[3])
        : "r"(a[0]), "r"(a[1]), "r"(a[2]), "r"(a[3]), "r"(b[0]), "r"(b[1]));
}

__device__ __forceinline__ void red2(float* p, float a, float b) {
    asm volatile("red.global.add.v2.f32 [%0], {%1, %2};" :: "l"(p), "f"(a), "f"(b) : "memory");
}

__device__ __forceinline__ uint32_t pk2(__nv_bfloat16 a, __nv_bfloat16 b) {
    __nv_bfloat162 t; t.x = a; t.y = b;
    return *(uint32_t*)&t;
}

__device__ __forceinline__ float ex2f_(float x) {
    float y; asm("ex2.approx.ftz.f32 %0, %1;" : "=f"(y) : "f"(x)); return y;
}
__device__ __forceinline__ float rcpf_(float x) {
    float y; asm("rcp.approx.ftz.f32 %0, %1;" : "=f"(y) : "f"(x)); return y;
}
__device__ __forceinline__ float fsig(float x)  { return rcpf_(1.f + ex2f_(-LOG2E * x)); }
__device__ __forceinline__ float ftanh(float x) { return 2.f * rcpf_(1.f + ex2f_(-2.f * LOG2E * x)) - 1.f; }

__device__ __forceinline__ uint32_t smem_u32(const void* p) {
    uint32_t a;
    asm("{ .reg .u64 t; cvta.to.shared.u64 t, %1; cvt.u32.u64 %0, t; }" : "=r"(a) : "l"(p));
    return a;
}
__device__ __forceinline__ void cpa16(uint32_t s, const void* g) {
    asm volatile("cp.async.cg.shared.global [%0], [%1], 16;" :: "r"(s), "l"(g) : "memory");
}

// ---------------- prep: gather x (fp32) + zero all GEMM accumulators ----------------
#define NXF4    (B*E/4)                              // 32768
#define NGF4    (B*G/4)                              // 196608 per gate buffer
#define ZERO_F4 (4*NGF4 + B*256/4 + B*64/4)          // 806912
#define PREP_BLOCKS ((NXF4 + ZERO_F4) / 256)         // 3280 exactly

__global__ void prep_kernel(const int* __restrict__ idx, const float* __restrict__ emb) {
    int i = blockIdx.x * 256 + threadIdx.x;
    if (i < NXF4) {
        int row = i >> 7;                            // E/4 = 128
        int c4  = (i & 127) * 4;
        float4 v = *(const float4*)(emb + (size_t)idx[row] * E + c4);
        *(float4*)(g_x + (size_t)row * E + c4) = v;
        return;
    }
    int j = i - NXF4;
    float4 z = make_float4(0.f, 0.f, 0.f, 0.f);
    if      (j < 1*NGF4) ((float4*)g_gi )[j]          = z;
    else if (j < 2*NGF4) ((float4*)g_gh )[j - 1*NGF4] = z;
    else if (j < 3*NGF4) ((float4*)g_gh2)[j - 2*NGF4] = z;
    else if (j < 4*NGF4) ((float4*)g_gi1)[j - 3*NGF4] = z;
    else if (j < 4*NGF4 + B*256/4) ((float4*)g_p0)[j - 4*NGF4] = z;
    else                 ((float4*)g_p1f)[j - 4*NGF4 - B*256/4] = z;
}

// ---------------- TF32 GEMM body: BM=64, BN=128, BK=32, 256 threads ----------------
// 8 warps (2m x 4n), warp tile 32x32. 2-stage cp.async. nmax masks the N range.
// C[m0:m0+64, n0:n0+min(128,nmax-n0)] += A @ W^T (red.global output)
#define TILE_A (64 * 36)               // floats
#define TILE_W (128 * 36)
#define STAGE_F (TILE_A + TILE_W)      // 6912 floats = 27648 B
#define SMEM_GEMM (2 * STAGE_F * 4)    // 55296 B

__device__ __forceinline__ void gemm_body(
    const float* __restrict__ A,
    const float* __restrict__ W, int K, int k0s, int npanels,
    float* __restrict__ C, int ldC, int n0, int m0, int nmax)
{
    extern __shared__ float dsm[];
    const int tid = threadIdx.x, lane = tid & 31, warp = tid >> 5;
    const int mwB = (warp & 1) * 32;
    const int nwB = (warp >> 1) * 32;

    const int wrow = tid >> 1;            // 0..127  W load row
    const int wcf  = (tid & 1) * 16;
    const int arow = (tid & 127) >> 1;    // 0..63   A load row (tid<128)

    float acc[2][4][4];
#pragma unroll
    for (int a = 0; a < 2; a++)
#pragma unroll
        for (int b = 0; b < 4; b++)
#pragma unroll
            for (int c = 0; c < 4; c++) acc[a][b][c] = 0.f;

    {
        int k0 = k0s;
        float* S = dsm;
        int gr = n0 + wrow; if (gr >= nmax) gr = nmax - 1;
        const float* gw = W + (size_t)gr * K + k0 + wcf;
        uint32_t sw = smem_u32(S + TILE_A + wrow * 36 + wcf);
#pragma unroll
        for (int c = 0; c < 4; c++) cpa16(sw + c * 16, gw + c * 4);
        if (tid < 128) {
            const float* ga = A + (size_t)(m0 + arow) * K + k0 + wcf;
            uint32_t sa = smem_u32(S + arow * 36 + wcf);
#pragma unroll
            for (int c = 0; c < 4; c++) cpa16(sa + c * 16, ga + c * 4);
        }
        asm volatile("cp.async.commit_group;" ::: "memory");
    }

    for (int p = 0; p < npanels; p++) {
        if (p + 1 < npanels) {
            int k0 = k0s + (p + 1) * 32;
            float* S = dsm + ((p + 1) & 1) * STAGE_F;
            int gr = n0 + wrow; if (gr >= nmax) gr = nmax - 1;
            const float* gw = W + (size_t)gr * K + k0 + wcf;
            uint32_t sw = smem_u32(S + TILE_A + wrow * 36 + wcf);
#pragma unroll
            for (int c = 0; c < 4; c++) cpa16(sw + c * 16, gw + c * 4);
            if (tid < 128) {
                const float* ga = A + (size_t)(m0 + arow) * K + k0 + wcf;
                uint32_t sa = smem_u32(S + arow * 36 + wcf);
#pragma unroll
                for (int c = 0; c < 4; c++) cpa16(sa + c * 16, ga + c * 4);
            }
            asm volatile("cp.async.commit_group;" ::: "memory");
            asm volatile("cp.async.wait_group 1;" ::: "memory");
        } else {
            asm volatile("cp.async.wait_group 0;" ::: "memory");
        }
        __syncthreads();

        const float* Ac = dsm + (p & 1) * STAGE_F;
        const float* Wc = Ac + TILE_A;
#pragma unroll
        for (int ks = 0; ks < 4; ks++) {
            const int cb = ks * 8 + (lane & 3);
            uint32_t a[2][4], b[4][2];
#pragma unroll
            for (int mt = 0; mt < 2; mt++) {
                int r = mwB + mt * 16 + (lane >> 2);
                a[mt][0] = __float_as_uint(Ac[r * 36 + cb]);
                a[mt][1] = __float_as_uint(Ac[(r + 8) * 36 + cb]);
                a[mt][2] = __float_as_uint(Ac[r * 36 + cb + 4]);
                a[mt][3] = __float_as_uint(Ac[(r + 8) * 36 + cb + 4]);
            }
#pragma unroll
            for (int nt = 0; nt < 4; nt++) {
                int n = nwB + nt * 8 + (lane >> 2);
                b[nt][0] = __float_as_uint(Wc[n * 36 + cb]);
                b[nt][1] = __float_as_uint(Wc[n * 36 + cb + 4]);
            }
#pragma unroll
            for (int mt = 0; mt < 2; mt++)
#pragma unroll
                for (int nt = 0; nt < 4; nt++)
                    mma_tf32(acc[mt][nt], a[mt], b[nt]);
        }
        __syncthreads();
    }

#pragma unroll
    for (int mt = 0; mt < 2; mt++) {
        int rg = m0 + mwB + mt * 16 + (lane >> 2);
#pragma unroll
        for (int nt = 0; nt < 4; nt++) {
            int c = n0 + nwB + nt * 8 + (lane & 3) * 2;
            if (c < nmax) {
                red2(C + (size_t)rg * ldC + c,       acc[mt][nt][0], acc[mt][nt][1]);
                red2(C + (size_t)(rg + 8) * ldC + c, acc[mt][nt][2], acc[mt][nt][3]);
            }
        }
    }
}

// ---------------- fused launch: gi0, gh0, gh1 (3 GEMMs x 4 k-splits) ----------------
__global__ __launch_bounds__(256) void gemm3_fused(const float* __restrict__ hidden,
                                                   const float* __restrict__ w_ih0,
                                                   const float* __restrict__ w_hh0,
                                                   const float* __restrict__ w_hh1) {
    int z = blockIdx.z, which = z >> 2, ks = z & 3;
    const float *Ag, *W;
    float* C;
    int K;
    if (which == 0)      { Ag = g_x;         W = w_ih0; C = g_gi;  K = E; }
    else if (which == 1) { Ag = hidden;      W = w_hh0; C = g_gh;  K = H; }
    else                 { Ag = hidden + BH; W = w_hh1; C = g_gh2; K = H; }
    int kc = K / 4;
    gemm_body(Ag, W, K, ks * kc, kc / 32, C, G, blockIdx.x * 128, blockIdx.y * 64, G);
}

// ---------------- single GEMM (gi1) with 4-way k-split ----------------
__global__ __launch_bounds__(256) void gemm1_ksplit(const float* __restrict__ h0,
                                                    const float* __restrict__ w_ih1) {
    int ks = blockIdx.z;
    gemm_body(h0, w_ih1, H, ks * (H / 4), (H / 4) / 32,
              g_gi1, G, blockIdx.x * 128, blockIdx.y * 64, G);
}

// ---------------- fused projections (8-way k-split) ----------------
__global__ __launch_bounds__(256) void proj_fused(const float* __restrict__ h1,
                                                  const float* __restrict__ t0_proj,
                                                  const float* __restrict__ t1_proj) {
    int x = blockIdx.x, ks = blockIdx.z;
    if (x < 2) {
        gemm_body(h1, t0_proj, H, ks * (H / 8), (H / 8) / 32,
                  g_p0, 256, x * 128, blockIdx.y * 64, 256);
    } else {
        gemm_body(h1, t1_proj, H, ks * (H / 8), (H / 8) / 32,
                  g_p1f, 64, 0, blockIdx.y * 64, 64);
    }
}

// ---------------- p1 fp32 -> bf16 (one-time; 16384 elems; 8 blocks) ----------------
__global__ void conv_p1_kernel() {
    int i = blockIdx.x * 256 + threadIdx.x;
    size_t base = (size_t)i * 8;
    float4 v0 = *(const float4*)(g_p1f + base);
    float4 v1 = *(const float4*)(g_p1f + base + 4);
    *(uint4*)(g_p1b + base) = make_uint4(
        pk2(__float2bfloat16(v0.x), __float2bfloat16(v0.y)),
        pk2(__float2bfloat16(v0.z), __float2bfloat16(v0.w)),
        pk2(__float2bfloat16(v1.x), __float2bfloat16(v1.y)),
        pk2(__float2bfloat16(v1.z), __float2bfloat16(v1.w)));
}

// ---------------- GRU gate fusion ----------------
__global__ void gates_kernel(const float* __restrict__ gi_, const float* __restrict__ gh_,
                             const float* __restrict__ b_ih, const float* __restrict__ b_hh,
                             const float* __restrict__ hprev,
                             float* __restrict__ hout) {
    int i = blockIdx.x * 256 + threadIdx.x;    // over B*H
    int m = i >> 10, j = i & 1023;
    const float* gi = gi_ + (size_t)m * G;
    const float* gh = gh_ + (size_t)m * G;
    float ir  = gi[j]         + b_ih[j];
    float iz  = gi[j + H]     + b_ih[j + H];
    float in_ = gi[j + 2 * H] + b_ih[j + 2 * H];
    float hr  = gh[j]         + b_hh[j];
    float hz  = gh[j + H]     + b_hh[j + H];
    float hn  = gh[j + 2 * H] + b_hh[j + 2 * H];
    float r = fsig(ir + hr);
    float z = fsig(iz + hz);
    float n = ftanh(in_ + r * hn);
    hout[i] = (1.f - z) * n + z * hprev[i];
}

// ---------------- head: logits[12] + log_softmax ----------------
__global__ void head_kernel(const float* __restrict__ h1, const float* __restrict__ hw) {
    __shared__ float sh[12];
    __shared__ float slse;
    int m = blockIdx.x;
    int tid = threadIdx.x, lane = tid & 31, w = tid >> 5;
    if (w < 12) {
        float s = 0.f;
        const float* hr = h1 + (size_t)m * H;
        const float* wr = hw + (size_t)w * H;
        for (int k = lane; k < H; k += 32) s += hr[k] * wr[k];
#pragma unroll
        for (int o = 16; o; o >>= 1) s += __shfl_xor_sync(0xffffffffu, s, o);
        if (lane == 0) sh[w] = s;
    }
    __syncthreads();
    if (tid == 0) {
        float mx = sh[0];
        for (int j = 1; j < 12; j++) mx = fmaxf(mx, sh[j]);
        float s = 0.f;
        for (int j = 0; j < 12; j++) s += expf(sh[j] - mx);
        slse = mx + logf(s);
    }
    __syncthreads();
    if (tid < 12) g_head[m * 12 + tid] = sh[tid] - slse;
}

// ---------------- cluster-0 (2-way) + prediction prefix cols 0..11 ----------------
__global__ void c0_kernel(const float* __restrict__ t0_out, float* __restrict__ outp) {
    __shared__ float sh[2];
    int m = blockIdx.x;
    int tid = threadIdx.x, lane = tid & 31, w = tid >> 5;
    if (w < 2) {
        float s = 0.f;
        const float* pr = g_p0 + (size_t)m * 256;
        const float* wr = t0_out + (size_t)w * 256;
        for (int k = lane; k < 256; k += 32) s += pr[k] * wr[k];
#pragma unroll
        for (int o = 16; o; o >>= 1) s += __shfl_xor_sync(0xffffffffu, s, o);
        if (lane == 0) sh[w] = s;
    }
    __syncthreads();
    if (tid < 12) {
        float* orow = outp + (size_t)m * V;
        if (tid < 10) {
            orow[tid] = g_head[m * 12 + tid];
        } else {
            float a = sh[0], b = sh[1];
            float mx = fmaxf(a, b);
            float lse = mx + logf(expf(a - mx) + expf(b - mx));
            orow[tid] = sh[tid - 10] - lse + g_head[m * 12 + 10];
        }
    }
}

// ---------------- tail GEMM [256,VT] = p1[256,64] @ t1_out[VT,64]^T (bf16) ----------------
__global__ __launch_bounds__(256) void tail_kernel(
    const float* __restrict__ Wt, float* __restrict__ outp, int pass)
{
    __shared__ __nv_bfloat16 Pb[256][72];
    __shared__ __nv_bfloat16 Wb[64][72];
    const int tid = threadIdx.x, lane = tid & 31, warp = tid >> 5;
    const int n0 = blockIdx.x * 64;
    const bool full = (n0 + 64 <= VT);

    // load P (g_p1b bf16, pre-converted): 256x64
#pragma unroll
    for (int it = 0; it < 8; it++) {
        int i = tid + it * 256;
        int row = i >> 3, c8 = (i & 7) * 8;
        *(uint4*)&Pb[row][c8] = *(const uint4*)(g_p1b + (size_t)row * 64 + c8);
    }
    // load W chunk: 64 rows x 64 cols fp32 -> bf16 (OOB rows -> 0)
#pragma unroll
    for (int it = 0; it < 4; it++) {
        int i = tid + it * 256;
        int row = i >> 4, f4 = (i & 15) * 4;
        int gidx = n0 + row;
        float4 v = make_float4(0.f, 0.f, 0.f, 0.f);
        if (gidx < VT) v = *(const float4*)(Wt + (size_t)gidx * 64 + f4);
        *(uint2*)&Wb[row][f4] = make_uint2(
            pk2(__float2bfloat16(v.x), __float2bfloat16(v.y)),
            pk2(__float2bfloat16(v.z), __float2bfloat16(v.w)));
    }
    __syncthreads();

    float acc[2][8][4];
#pragma unroll
    for (int a = 0; a < 2; a++)
#pragma unroll
        for (int b = 0; b < 8; b++)
#pragma unroll
            for (int c = 0; c < 4; c++) acc[a][b][c] = 0.f;

#pragma unroll
    for (int ks = 0; ks < 4; ks++) {
        const int cb = ks * 16 + (lane & 3) * 2;
        uint32_t a[2][4], b[8][2];
#pragma unroll
        for (int mt = 0; mt < 2; mt++) {
            int r = warp * 32 + mt * 16 + (lane >> 2);
            a[mt][0] = *(const uint32_t*)&Pb[r][cb];
            a[mt][1] = *(const uint32_t*)&Pb[r + 8][cb];
            a[mt][2] = *(const uint32_t*)&Pb[r][cb + 8];
            a[mt][3] = *(const uint32_t*)&Pb[r + 8][cb + 8];
        }
#pragma unroll
        for (int nt = 0; nt < 8; nt++) {
            int n = nt * 8 + (lane >> 2);
            b[nt][0] = *(const uint32_t*)&Wb[n][cb];
            b[nt][1] = *(const uint32_t*)&Wb[n][cb + 8];
        }
#pragma unroll
        for (int mt = 0; mt < 2; mt++)
#pragma unroll
            for (int nt = 0; nt < 8; nt++)
                mma16816(acc[mt][nt], a[mt], b[nt]);
    }

    if (pass == 0) {
#pragma unroll
        for (int j = 0; j < 4; j++) {
            int mt = j >> 1, hf = j & 1;
            int r = warp * 32 + (lane >> 2) + hf * 8 + mt * 16;
            float ss = 0.f;
            if (full) {
#pragma unroll
                for (int nt = 0; nt < 8; nt++) {
                    ss += ex2f_(LOG2E * acc[mt][nt][hf * 2]);
                    ss += ex2f_(LOG2E * acc[mt][nt][hf * 2 + 1]);
                }
            } else {
#pragma unroll
                for (int nt = 0; nt < 8; nt++)
#pragma unroll
                    for (int e = 0; e < 2; e++) {
                        int gcol = n0 + nt * 8 + (lane & 3) * 2 + e;
                        if (gcol < VT) ss += ex2f_(LOG2E * acc[mt][nt][hf * 2 + e]);
                    }
            }
            ss += __shfl_xor_sync(0xffffffffu, ss, 1);
            ss += __shfl_xor_sync(0xffffffffu, ss, 2);
            if ((lane & 3) == 0)
                g_psum[(size_t)r * TSTRIDE + blockIdx.x] = ss;
        }
    } else {
#pragma unroll
        for (int j = 0; j < 4; j++) {
            int mt = j >> 1, hf = j & 1;
            int r = warp * 32 + (lane >> 2) + hf * 8 + mt * 16;
            float ofs = g_off[r];
            float* orow = outp + (size_t)r * V + 12;
#pragma unroll
            for (int nt = 0; nt < 8; nt++) {
                int c = n0 + nt * 8 + (lane & 3) * 2;
                float v0 = acc[mt][nt][hf * 2] + ofs;
                float v1 = acc[mt][nt][hf * 2 + 1] + ofs;
                if (full) {
                    *(float2*)(orow + c) = make_float2(v0, v1);
                } else {
                    if (c < VT)     orow[c] = v0;
                    if (c + 1 < VT) orow[c + 1] = v1;
                }
            }
        }
    }
}

// ---------------- combine tail partial sums into per-row offset ----------------
__global__ void combine_kernel() {
    int m = blockIdx.x;
    int tid = threadIdx.x;
    float s = 0.f;
    for (int b = tid; b < TNB; b += 256)
        s += g_psum[(size_t)m * TSTRIDE + b];
    __shared__ float sh[256];
    sh[tid] = s;
    __syncthreads();
    for (int o = 128; o; o >>= 1) {
        if (tid < o) sh[tid] += sh[tid + o];
        __syncthreads();
    }
    if (tid == 0) g_off[m] = g_head[m * 12 + 11] - logf(sh[0]);
}

// ---------------- launch ----------------
extern "C" void kernel_launch(void* const* d_in, const int* in_sizes, int n_in,
                              void* d_out, int out_size) {
    const int*   input  = (const int*)  d_in[0];
    const float* hidden = (const float*)d_in[1];
    // d_in[2] = start_state (unused by reference)
    const float* emb    = (const float*)d_in[3];
    const float* w_ih0  = (const float*)d_in[4];
    const float* w_hh0  = (const float*)d_in[5];
    const float* b_ih0  = (const float*)d_in[6];
    const float* b_hh0  = (const float*)d_in[7];
    const float* w_ih1  = (const float*)d_in[8];
    const float* w_hh1  = (const float*)d_in[9];
    const float* b_ih1  = (const float*)d_in[10];
    const float* b_hh1  = (const float*)d_in[11];
    const float* head_w = (const float*)d_in[12];
    const float* t0_proj= (const float*)d_in[13];
    const float* t0_out = (const float*)d_in[14];
    const float* t1_proj= (const float*)d_in[15];
    const float* t1_out = (const float*)d_in[16];
    float* out = (float*)d_out;

    cudaFuncSetAttribute(gemm3_fused,  cudaFuncAttributeMaxDynamicSharedMemorySize, SMEM_GEMM);
    cudaFuncSetAttribute(gemm1_ksplit, cudaFuncAttributeMaxDynamicSharedMemorySize, SMEM_GEMM);
    cudaFuncSetAttribute(proj_fused,   cudaFuncAttributeMaxDynamicSharedMemorySize, SMEM_GEMM);

    float *pgi, *pgh, *pgh2, *pgi1, *ph0b, *ph1b;
    cudaGetSymbolAddress((void**)&pgi,  g_gi);
    cudaGetSymbolAddress((void**)&pgh,  g_gh);
    cudaGetSymbolAddress((void**)&pgh2, g_gh2);
    cudaGetSymbolAddress((void**)&pgi1, g_gi1);
    cudaGetSymbolAddress((void**)&ph0b, g_h0buf);
    cudaGetSymbolAddress((void**)&ph1b, g_h1buf);

    bool has_hidden = (out_size >= BV + 2 * BH);
    float* h0 = has_hidden ? out + (size_t)BV : ph0b;
    float* h1 = has_hidden ? out + (size_t)BV + BH : ph1b;

    // 0: gather x (fp32) + zero accumulators
    prep_kernel<<<PREP_BLOCKS, 256>>>(input, emb);
    // 1: gi0, gh0, gh1 fused (tf32, BN=128, 3 GEMMs x 4 k-splits, 1152 blocks)
    gemm3_fused<<<dim3(24, 4, 12), 256, SMEM_GEMM>>>(hidden, w_ih0, w_hh0, w_hh1);
    // 2: gates layer 0 -> h0
    gates_kernel<<<BH / 256, 256>>>(pgi, pgh, b_ih0, b_hh0, hidden, h0);
    // 3: gi1 = h0 @ w_ih1^T (tf32, BN=128, 4-way k-split, 384 blocks)
    gemm1_ksplit<<<dim3(24, 4, 4), 256, SMEM_GEMM>>>(h0, w_ih1);
    // 4: gates layer 1 -> h1
    gates_kernel<<<BH / 256, 256>>>(pgi1, pgh2, b_ih1, b_hh1, hidden + BH, h1);
    // 5: p0/p1 projections fused (tf32, 8-way k-split, 96 blocks)
    proj_fused<<<dim3(3, 4, 8), 256, SMEM_GEMM>>>(h1, t0_proj, t1_proj);
    // 6: p1 fp32 -> bf16 (tiny one-time convert)
    conv_p1_kernel<<<(B * 64 / 8) / 256, 256>>>();
    // 7: head log-softmax
    head_kernel<<<B, 384>>>(h1, head_w);
    // 8: cluster 0 + output prefix
    c0_kernel<<<B, 64>>>(t0_out, out);
    // 9: tail pass 0 (sumexp partials, BN=64, 2000 blocks)
    tail_kernel<<<TNB, 256>>>(t1_out, out, 0);
    // 10: combine -> per-row offset
    combine_kernel<<<B, 256>>>();
    // 11: tail pass 1 (write log-probs)
    tail_kernel<<<TNB, 256>>>(t1_out, out, 1);
}

// round 17
// speedup vs baseline: 1.0881x; 1.0125x over previous
#include <cuda_runtime.h>
#include <cuda_bf16.h>
#include <cstdint>

#define B 256
#define E 512
#define H 1024
#define G 3072          // 3*H
#define V 128000
#define VT 127988       // V - 12
#define BV (B*V)
#define BH (B*H)
#define TNB 2000        // tail blocks (BN=64)
#define TSTRIDE 2048
#define LOG2E 1.4426950408889634f

// ---------------- scratch (device globals; no allocations allowed) ----------------
__device__ __align__(16) float g_x[B*E];        // gathered embedding (fp32)
__device__ __align__(16) float g_gi[B*G];       // gi0 accumulator
__device__ __align__(16) float g_gh[B*G];       // gh0 accumulator
__device__ __align__(16) float g_gh2[B*G];      // gh1 accumulator
__device__ __align__(16) float g_gi1[B*G];      // gi1 accumulator
__device__ __align__(16) float g_p0[B*256];
__device__ __align__(16) float g_p1f[B*64];
__device__ __align__(16) __nv_bfloat16 g_p1b[B*64];
__device__ float g_head[B*12];      // log-softmaxed head
__device__ float g_off[B];          // head_lp[:,11] - lse_tail
__device__ float g_psum[B*TSTRIDE];
__device__ float g_h0buf[BH], g_h1buf[BH];   // fallback if d_out lacks hidden region

// ---------------- helpers ----------------
__device__ __forceinline__ void mma16816(float* d, const uint32_t* a, const uint32_t* b) {
    asm volatile(
        "mma.sync.aligned.m16n8k16.row.col.f32.bf16.bf16.f32 "
        "{%0,%1,%2,%3}, {%4,%5,%6,%7}, {%8,%9}, {%0,%1,%2,%3};\n"
        : "+f"(d[0]), "+f"(d[1]), "+f"(d[2]), "+f"(d[3])
        : "r"(a[0]), "r"(a[1]), "r"(a[2]), "r"(a[3]), "r"(b[0]), "r"(b[1]));
}

// tf32 MMA: operands are fp32 bit patterns (HW uses top 19 bits)
__device__ __forceinline__ void mma_tf32(float* d, const uint32_t* a, const uint32_t* b) {
    asm volatile(
        "mma.sync.aligned.m16n8k8.row.col.f32.tf32.tf32.f32 "
        "{%0,%1,%2,%3}, {%4,%5,%6,%7}, {%8,%9}, {%0,%1,%2,%3};\n"
        : "+f"(d[0]), "+f"(d[1]), "+f"(d[2]), "+f"(d[3])
        : "r"(a[0]), "r"(a[1]), "r"(a[2]), "r"(a[3]), "r"(b[0]), "r"(b[1]));
}

__device__ __forceinline__ void red2(float* p, float a, float b) {
    asm volatile("red.global.add.v2.f32 [%0], {%1, %2};" :: "l"(p), "f"(a), "f"(b) : "memory");
}

__device__ __forceinline__ uint32_t pk2(__nv_bfloat16 a, __nv_bfloat16 b) {
    __nv_bfloat162 t; t.x = a; t.y = b;
    return *(uint32_t*)&t;
}

__device__ __forceinline__ float ex2f_(float x) {
    float y; asm("ex2.approx.ftz.f32 %0, %1;" : "=f"(y) : "f"(x)); return y;
}
__device__ __forceinline__ float rcpf_(float x) {
    float y; asm("rcp.approx.ftz.f32 %0, %1;" : "=f"(y) : "f"(x)); return y;
}
__device__ __forceinline__ float fsig(float x)  { return rcpf_(1.f + ex2f_(-LOG2E * x)); }
__device__ __forceinline__ float ftanh(float x) { return 2.f * rcpf_(1.f + ex2f_(-2.f * LOG2E * x)) - 1.f; }

__device__ __forceinline__ uint32_t smem_u32(const void* p) {
    uint32_t a;
    asm("{ .reg .u64 t; cvta.to.shared.u64 t, %1; cvt.u32.u64 %0, t; }" : "=r"(a) : "l"(p));
    return a;
}
__device__ __forceinline__ void cpa16(uint32_t s, const void* g) {
    asm volatile("cp.async.cg.shared.global [%0], [%1], 16;" :: "r"(s), "l"(g) : "memory");
}

// ---------------- prep: gather x (fp32) + zero all GEMM accumulators ----------------
#define NXF4    (B*E/4)                              // 32768
#define NGF4    (B*G/4)                              // 196608 per gate buffer
#define ZERO_F4 (4*NGF4 + B*256/4 + B*64/4)          // 806912
#define PREP_BLOCKS ((NXF4 + ZERO_F4) / 256)         // 3280 exactly

__global__ void prep_kernel(const int* __restrict__ idx, const float* __restrict__ emb) {
    int i = blockIdx.x * 256 + threadIdx.x;
    if (i < NXF4) {
        int row = i >> 7;                            // E/4 = 128
        int c4  = (i & 127) * 4;
        float4 v = *(const float4*)(emb + (size_t)idx[row] * E + c4);
        *(float4*)(g_x + (size_t)row * E + c4) = v;
        return;
    }
    int j = i - NXF4;
    float4 z = make_float4(0.f, 0.f, 0.f, 0.f);
    if      (j < 1*NGF4) ((float4*)g_gi )[j]          = z;
    else if (j < 2*NGF4) ((float4*)g_gh )[j - 1*NGF4] = z;
    else if (j < 3*NGF4) ((float4*)g_gh2)[j - 2*NGF4] = z;
    else if (j < 4*NGF4) ((float4*)g_gi1)[j - 3*NGF4] = z;
    else if (j < 4*NGF4 + B*256/4) ((float4*)g_p0)[j - 4*NGF4] = z;
    else                 ((float4*)g_p1f)[j - 4*NGF4 - B*256/4] = z;
}

// ---------------- TF32 GEMM body: BM=128, BN=128, BK=32, 256 threads ----------------
// 8 warps (4m x 2n), warp tile 32x64. 2-stage cp.async. nmax masks the N range.
// C[m0:m0+128, n0:n0+min(128,nmax-n0)] += A @ W^T (red.global output)
#define TILE_F  (128 * 36)             // floats per tile (A or W)
#define STAGE_F (2 * TILE_F)           // 9216 floats = 36864 B
#define SMEM_GEMM (2 * STAGE_F * 4)    // 73728 B

__device__ __forceinline__ void gemm_body(
    const float* __restrict__ A,
    const float* __restrict__ W, int K, int k0s, int npanels,
    float* __restrict__ C, int ldC, int n0, int m0, int nmax)
{
    extern __shared__ float dsm[];
    const int tid = threadIdx.x, lane = tid & 31, warp = tid >> 5;
    const int mwB = (warp & 3) * 32;      // 4 m-groups
    const int nwB = (warp >> 2) * 64;     // 2 n-groups

    const int row2 = tid >> 1;            // 0..127 load row (A and W)
    const int cf   = (tid & 1) * 16;      // 16-float half-row

    float acc[2][8][4];
#pragma unroll
    for (int a = 0; a < 2; a++)
#pragma unroll
        for (int b = 0; b < 8; b++)
#pragma unroll
            for (int c = 0; c < 4; c++) acc[a][b][c] = 0.f;

    {
        int k0 = k0s;
        float* S = dsm;
        const float* ga = A + (size_t)(m0 + row2) * K + k0 + cf;
        int gr = n0 + row2; if (gr >= nmax) gr = nmax - 1;
        const float* gw = W + (size_t)gr * K + k0 + cf;
        uint32_t sa = smem_u32(S + row2 * 36 + cf);
        uint32_t sw = smem_u32(S + TILE_F + row2 * 36 + cf);
#pragma unroll
        for (int c = 0; c < 4; c++) {
            cpa16(sa + c * 16, ga + c * 4);
            cpa16(sw + c * 16, gw + c * 4);
        }
        asm volatile("cp.async.commit_group;" ::: "memory");
    }

    for (int p = 0; p < npanels; p++) {
        if (p + 1 < npanels) {
            int k0 = k0s + (p + 1) * 32;
            float* S = dsm + ((p + 1) & 1) * STAGE_F;
            const float* ga = A + (size_t)(m0 + row2) * K + k0 + cf;
            int gr = n0 + row2; if (gr >= nmax) gr = nmax - 1;
            const float* gw = W + (size_t)gr * K + k0 + cf;
            uint32_t sa = smem_u32(S + row2 * 36 + cf);
            uint32_t sw = smem_u32(S + TILE_F + row2 * 36 + cf);
#pragma unroll
            for (int c = 0; c < 4; c++) {
                cpa16(sa + c * 16, ga + c * 4);
                cpa16(sw + c * 16, gw + c * 4);
            }
            asm volatile("cp.async.commit_group;" ::: "memory");
            asm volatile("cp.async.wait_group 1;" ::: "memory");
        } else {
            asm volatile("cp.async.wait_group 0;" ::: "memory");
        }
        __syncthreads();

        const float* Ac = dsm + (p & 1) * STAGE_F;
        const float* Wc = Ac + TILE_F;
#pragma unroll
        for (int ks = 0; ks < 4; ks++) {
            const int cb = ks * 8 + (lane & 3);
            uint32_t a[2][4], b[8][2];
#pragma unroll
            for (int mt = 0; mt < 2; mt++) {
                int r = mwB + mt * 16 + (lane >> 2);
                a[mt][0] = __float_as_uint(Ac[r * 36 + cb]);
                a[mt][1] = __float_as_uint(Ac[(r + 8) * 36 + cb]);
                a[mt][2] = __float_as_uint(Ac[r * 36 + cb + 4]);
                a[mt][3] = __float_as_uint(Ac[(r + 8) * 36 + cb + 4]);
            }
#pragma unroll
            for (int nt = 0; nt < 8; nt++) {
                int n = nwB + nt * 8 + (lane >> 2);
                b[nt][0] = __float_as_uint(Wc[n * 36 + cb]);
                b[nt][1] = __float_as_uint(Wc[n * 36 + cb + 4]);
            }
#pragma unroll
            for (int mt = 0; mt < 2; mt++)
#pragma unroll
                for (int nt = 0; nt < 8; nt++)
                    mma_tf32(acc[mt][nt], a[mt], b[nt]);
        }
        __syncthreads();
    }

#pragma unroll
    for (int mt = 0; mt < 2; mt++) {
        int rg = m0 + mwB + mt * 16 + (lane >> 2);
#pragma unroll
        for (int nt = 0; nt < 8; nt++) {
            int c = n0 + nwB + nt * 8 + (lane & 3) * 2;
            if (c < nmax) {
                red2(C + (size_t)rg * ldC + c,       acc[mt][nt][0], acc[mt][nt][1]);
                red2(C + (size_t)(rg + 8) * ldC + c, acc[mt][nt][2], acc[mt][nt][3]);
            }
        }
    }
}

// ---------------- fused launch: gi0, gh0, gh1 (3 GEMMs x 4 k-splits) ----------------
__global__ __launch_bounds__(256) void gemm3_fused(const float* __restrict__ hidden,
                                                   const float* __restrict__ w_ih0,
                                                   const float* __restrict__ w_hh0,
                                                   const float* __restrict__ w_hh1) {
    int z = blockIdx.z, which = z >> 2, ks = z & 3;
    const float *Ag, *W;
    float* C;
    int K;
    if (which == 0)      { Ag = g_x;         W = w_ih0; C = g_gi;  K = E; }
    else if (which == 1) { Ag = hidden;      W = w_hh0; C = g_gh;  K = H; }
    else                 { Ag = hidden + BH; W = w_hh1; C = g_gh2; K = H; }
    int kc = K / 4;
    gemm_body(Ag, W, K, ks * kc, kc / 32, C, G, blockIdx.x * 128, blockIdx.y * 128, G);
}

// ---------------- single GEMM (gi1) with 4-way k-split ----------------
__global__ __launch_bounds__(256) void gemm1_ksplit(const float* __restrict__ h0,
                                                    const float* __restrict__ w_ih1) {
    int ks = blockIdx.z;
    gemm_body(h0, w_ih1, H, ks * (H / 4), (H / 4) / 32,
              g_gi1, G, blockIdx.x * 128, blockIdx.y * 128, G);
}

// ---------------- fused projections (8-way k-split) ----------------
__global__ __launch_bounds__(256) void proj_fused(const float* __restrict__ h1,
                                                  const float* __restrict__ t0_proj,
                                                  const float* __restrict__ t1_proj) {
    int x = blockIdx.x, ks = blockIdx.z;
    if (x < 2) {
        gemm_body(h1, t0_proj, H, ks * (H / 8), (H / 8) / 32,
                  g_p0, 256, x * 128, blockIdx.y * 128, 256);
    } else {
        gemm_body(h1, t1_proj, H, ks * (H / 8), (H / 8) / 32,
                  g_p1f, 64, 0, blockIdx.y * 128, 64);
    }
}

// ---------------- p1 fp32 -> bf16 (one-time; 16384 elems; 8 blocks) ----------------
__global__ void conv_p1_kernel() {
    int i = blockIdx.x * 256 + threadIdx.x;
    size_t base = (size_t)i * 8;
    float4 v0 = *(const float4*)(g_p1f + base);
    float4 v1 = *(const float4*)(g_p1f + base + 4);
    *(uint4*)(g_p1b + base) = make_uint4(
        pk2(__float2bfloat16(v0.x), __float2bfloat16(v0.y)),
        pk2(__float2bfloat16(v0.z), __float2bfloat16(v0.w)),
        pk2(__float2bfloat16(v1.x), __float2bfloat16(v1.y)),
        pk2(__float2bfloat16(v1.z), __float2bfloat16(v1.w)));
}

// ---------------- GRU gate fusion ----------------
__global__ void gates_kernel(const float* __restrict__ gi_, const float* __restrict__ gh_,
                             const float* __restrict__ b_ih, const float* __restrict__ b_hh,
                             const float* __restrict__ hprev,
                             float* __restrict__ hout) {
    int i = blockIdx.x * 256 + threadIdx.x;    // over B*H
    int m = i >> 10, j = i & 1023;
    const float* gi = gi_ + (size_t)m * G;
    const float* gh = gh_ + (size_t)m * G;
    float ir  = gi[j]         + b_ih[j];
    float iz  = gi[j + H]     + b_ih[j + H];
    float in_ = gi[j + 2 * H] + b_ih[j + 2 * H];
    float hr  = gh[j]         + b_hh[j];
    float hz  = gh[j + H]     + b_hh[j + H];
    float hn  = gh[j + 2 * H] + b_hh[j + 2 * H];
    float r = fsig(ir + hr);
    float z = fsig(iz + hz);
    float n = ftanh(in_ + r * hn);
    hout[i] = (1.f - z) * n + z * hprev[i];
}

// ---------------- head: logits[12] + log_softmax ----------------
__global__ void head_kernel(const float* __restrict__ h1, const float* __restrict__ hw) {
    __shared__ float sh[12];
    __shared__ float slse;
    int m = blockIdx.x;
    int tid = threadIdx.x, lane = tid & 31, w = tid >> 5;
    if (w < 12) {
        float s = 0.f;
        const float* hr = h1 + (size_t)m * H;
        const float* wr = hw + (size_t)w * H;
        for (int k = lane; k < H; k += 32) s += hr[k] * wr[k];
#pragma unroll
        for (int o = 16; o; o >>= 1) s += __shfl_xor_sync(0xffffffffu, s, o);
        if (lane == 0) sh[w] = s;
    }
    __syncthreads();
    if (tid == 0) {
        float mx = sh[0];
        for (int j = 1; j < 12; j++) mx = fmaxf(mx, sh[j]);
        float s = 0.f;
        for (int j = 0; j < 12; j++) s += expf(sh[j] - mx);
        slse = mx + logf(s);
    }
    __syncthreads();
    if (tid < 12) g_head[m * 12 + tid] = sh[tid] - slse;
}

// ---------------- cluster-0 (2-way) + prediction prefix cols 0..11 ----------------
__global__ void c0_kernel(const float* __restrict__ t0_out, float* __restrict__ outp) {
    __shared__ float sh[2];
    int m = blockIdx.x;
    int tid = threadIdx.x, lane = tid & 31, w = tid >> 5;
    if (w < 2) {
        float s = 0.f;
        const float* pr = g_p0 + (size_t)m * 256;
        const float* wr = t0_out + (size_t)w * 256;
        for (int k = lane; k < 256; k += 32) s += pr[k] * wr[k];
#pragma unroll
        for (int o = 16; o; o >>= 1) s += __shfl_xor_sync(0xffffffffu, s, o);
        if (lane == 0) sh[w] = s;
    }
    __syncthreads();
    if (tid < 12) {
        float* orow = outp + (size_t)m * V;
        if (tid < 10) {
            orow[tid] = g_head[m * 12 + tid];
        } else {
            float a = sh[0], b = sh[1];
            float mx = fmaxf(a, b);
            float lse = mx + logf(expf(a - mx) + expf(b - mx));
            orow[tid] = sh[tid - 10] - lse + g_head[m * 12 + 10];
        }
    }
}

// ---------------- tail GEMM [256,VT] = p1[256,64] @ t1_out[VT,64]^T (bf16) ----------------
__global__ __launch_bounds__(256) void tail_kernel(
    const float* __restrict__ Wt, float* __restrict__ outp, int pass)
{
    __shared__ __nv_bfloat16 Pb[256][72];
    __shared__ __nv_bfloat16 Wb[64][72];
    const int tid = threadIdx.x, lane = tid & 31, warp = tid >> 5;
    const int n0 = blockIdx.x * 64;
    const bool full = (n0 + 64 <= VT);

    // load P (g_p1b bf16, pre-converted): 256x64
#pragma unroll
    for (int it = 0; it < 8; it++) {
        int i = tid + it * 256;
        int row = i >> 3, c8 = (i & 7) * 8;
        *(uint4*)&Pb[row][c8] = *(const uint4*)(g_p1b + (size_t)row * 64 + c8);
    }
    // load W chunk: 64 rows x 64 cols fp32 -> bf16 (OOB rows -> 0)
#pragma unroll
    for (int it = 0; it < 4; it++) {
        int i = tid + it * 256;
        int row = i >> 4, f4 = (i & 15) * 4;
        int gidx = n0 + row;
        float4 v = make_float4(0.f, 0.f, 0.f, 0.f);
        if (gidx < VT) v = *(const float4*)(Wt + (size_t)gidx * 64 + f4);
        *(uint2*)&Wb[row][f4] = make_uint2(
            pk2(__float2bfloat16(v.x), __float2bfloat16(v.y)),
            pk2(__float2bfloat16(v.z), __float2bfloat16(v.w)));
    }
    __syncthreads();

    float acc[2][8][4];
#pragma unroll
    for (int a = 0; a < 2; a++)
#pragma unroll
        for (int b = 0; b < 8; b++)
#pragma unroll
            for (int c = 0; c < 4; c++) acc[a][b][c] = 0.f;

#pragma unroll
    for (int ks = 0; ks < 4; ks++) {
        const int cb = ks * 16 + (lane & 3) * 2;
        uint32_t a[2][4], b[8][2];
#pragma unroll
        for (int mt = 0; mt < 2; mt++) {
            int r = warp * 32 + mt * 16 + (lane >> 2);
            a[mt][0] = *(const uint32_t*)&Pb[r][cb];
            a[mt][1] = *(const uint32_t*)&Pb[r + 8][cb];
            a[mt][2] = *(const uint32_t*)&Pb[r][cb + 8];
            a[mt][3] = *(const uint32_t*)&Pb[r + 8][cb + 8];
        }
#pragma unroll
        for (int nt = 0; nt < 8; nt++) {
            int n = nt * 8 + (lane >> 2);
            b[nt][0] = *(const uint32_t*)&Wb[n][cb];
            b[nt][1] = *(const uint32_t*)&Wb[n][cb + 8];
        }
#pragma unroll
        for (int mt = 0; mt < 2; mt++)
#pragma unroll
            for (int nt = 0; nt < 8; nt++)
                mma16816(acc[mt][nt], a[mt], b[nt]);
    }

    if (pass == 0) {
#pragma unroll
        for (int j = 0; j < 4; j++) {
            int mt = j >> 1, hf = j & 1;
            int r = warp * 32 + (lane >> 2) + hf * 8 + mt * 16;
            float ss = 0.f;
            if (full) {
#pragma unroll
                for (int nt = 0; nt < 8; nt++) {
                    ss += ex2f_(LOG2E * acc[mt][nt][hf * 2]);
                    ss += ex2f_(LOG2E * acc[mt][nt][hf * 2 + 1]);
                }
            } else {
#pragma unroll
                for (int nt = 0; nt < 8; nt++)
#pragma unroll
                    for (int e = 0; e < 2; e++) {
                        int gcol = n0 + nt * 8 + (lane & 3) * 2 + e;
                        if (gcol < VT) ss += ex2f_(LOG2E * acc[mt][nt][hf * 2 + e]);
                    }
            }
            ss += __shfl_xor_sync(0xffffffffu, ss, 1);
            ss += __shfl_xor_sync(0xffffffffu, ss, 2);
            if ((lane & 3) == 0)
                g_psum[(size_t)r * TSTRIDE + blockIdx.x] = ss;
        }
    } else {
#pragma unroll
        for (int j = 0; j < 4; j++) {
            int mt = j >> 1, hf = j & 1;
            int r = warp * 32 + (lane >> 2) + hf * 8 + mt * 16;
            float ofs = g_off[r];
            float* orow = outp + (size_t)r * V + 12;
#pragma unroll
            for (int nt = 0; nt < 8; nt++) {
                int c = n0 + nt * 8 + (lane & 3) * 2;
                float v0 = acc[mt][nt][hf * 2] + ofs;
                float v1 = acc[mt][nt][hf * 2 + 1] + ofs;
                if (full) {
                    *(float2*)(orow + c) = make_float2(v0, v1);
                } else {
                    if (c < VT)     orow[c] = v0;
                    if (c + 1 < VT) orow[c + 1] = v1;
                }
            }
        }
    }
}

// ---------------- combine tail partial sums into per-row offset ----------------
__global__ void combine_kernel() {
    int m = blockIdx.x;
    int tid = threadIdx.x;
    float s = 0.f;
    for (int b = tid; b < TNB; b += 256)
        s += g_psum[(size_t)m * TSTRIDE + b];
    __shared__ float sh[256];
    sh[tid] = s;
    __syncthreads();
    for (int o = 128; o; o >>= 1) {
        if (tid < o) sh[tid] += sh[tid + o];
        __syncthreads();
    }
    if (tid == 0) g_off[m] = g_head[m * 12 + 11] - logf(sh[0]);
}

// ---------------- launch ----------------
extern "C" void kernel_launch(void* const* d_in, const int* in_sizes, int n_in,
                              void* d_out, int out_size) {
    const int*   input  = (const int*)  d_in[0];
    const float* hidden = (const float*)d_in[1];
    // d_in[2] = start_state (unused by reference)
    const float* emb    = (const float*)d_in[3];
    const float* w_ih0  = (const float*)d_in[4];
    const float* w_hh0  = (const float*)d_in[5];
    const float* b_ih0  = (const float*)d_in[6];
    const float* b_hh0  = (const float*)d_in[7];
    const float* w_ih1  = (const float*)d_in[8];
    const float* w_hh1  = (const float*)d_in[9];
    const float* b_ih1  = (const float*)d_in[10];
    const float* b_hh1  = (const float*)d_in[11];
    const float* head_w = (const float*)d_in[12];
    const float* t0_proj= (const float*)d_in[13];
    const float* t0_out = (const float*)d_in[14];
    const float* t1_proj= (const float*)d_in[15];
    const float* t1_out = (const float*)d_in[16];
    float* out = (float*)d_out;

    cudaFuncSetAttribute(gemm3_fused,  cudaFuncAttributeMaxDynamicSharedMemorySize, SMEM_GEMM);
    cudaFuncSetAttribute(gemm1_ksplit, cudaFuncAttributeMaxDynamicSharedMemorySize, SMEM_GEMM);
    cudaFuncSetAttribute(proj_fused,   cudaFuncAttributeMaxDynamicSharedMemorySize, SMEM_GEMM);

    float *pgi, *pgh, *pgh2, *pgi1, *ph0b, *ph1b;
    cudaGetSymbolAddress((void**)&pgi,  g_gi);
    cudaGetSymbolAddress((void**)&pgh,  g_gh);
    cudaGetSymbolAddress((void**)&pgh2, g_gh2);
    cudaGetSymbolAddress((void**)&pgi1, g_gi1);
    cudaGetSymbolAddress((void**)&ph0b, g_h0buf);
    cudaGetSymbolAddress((void**)&ph1b, g_h1buf);

    bool has_hidden = (out_size >= BV + 2 * BH);
    float* h0 = has_hidden ? out + (size_t)BV : ph0b;
    float* h1 = has_hidden ? out + (size_t)BV + BH : ph1b;

    // 0: gather x (fp32) + zero accumulators
    prep_kernel<<<PREP_BLOCKS, 256>>>(input, emb);
    // 1: gi0, gh0, gh1 fused (tf32, BM=128/BN=128, 3 GEMMs x 4 k-splits, 576 blocks)
    gemm3_fused<<<dim3(24, 2, 12), 256, SMEM_GEMM>>>(hidden, w_ih0, w_hh0, w_hh1);
    // 2: gates layer 0 -> h0
    gates_kernel<<<BH / 256, 256>>>(pgi, pgh, b_ih0, b_hh0, hidden, h0);
    // 3: gi1 = h0 @ w_ih1^T (tf32, BM=128/BN=128, 4-way k-split, 192 blocks)
    gemm1_ksplit<<<dim3(24, 2, 4), 256, SMEM_GEMM>>>(h0, w_ih1);
    // 4: gates layer 1 -> h1
    gates_kernel<<<BH / 256, 256>>>(pgi1, pgh2, b_ih1, b_hh1, hidden + BH, h1);
    // 5: p0/p1 projections fused (tf32, 8-way k-split, 48 blocks)
    proj_fused<<<dim3(3, 2, 8), 256, SMEM_GEMM>>>(h1, t0_proj, t1_proj);
    // 6: p1 fp32 -> bf16 (tiny one-time convert)
    conv_p1_kernel<<<(B * 64 / 8) / 256, 256>>>();
    // 7: head log-softmax
    head_kernel<<<B, 384>>>(h1, head_w);
    // 8: cluster 0 + output prefix
    c0_kernel<<<B, 64>>>(t0_out, out);
    // 9: tail pass 0 (sumexp partials, BN=64, 2000 blocks)
    tail_kernel<<<TNB, 256>>>(t1_out, out, 0);
    // 10: combine -> per-row offset
    combine_kernel<<<B, 256>>>();
    // 11: tail pass 1 (write log-probs)
    tail_kernel<<<TNB, 256>>>(t1_out, out, 1);
}